// round 13
// baseline (speedup 1.0000x reference)
#include <cuda_runtime.h>
#include <cuda.h>
#include <cuda_fp16.h>
#include <cstdint>

#define BATCH 2
#define SEQ   2048
#define DMODEL 1024
#define NHEAD 16
#define DHEAD 64
#define MTOT  (BATCH*SEQ)          // 4096
#define BHTOT (BATCH*NHEAD)        // 32
#define QKVPART ((size_t)BHTOT*SEQ*DHEAD)

// 0.125 * log2(e), folded into Wq/bq at preprocessing time.
#define QSCALE 0.1803368801111832f

// ---------------------------------------------------------------------------
// Device scratch
// ---------------------------------------------------------------------------
__device__ __half g_act[3u*MTOT*DMODEL];       // activations fp16 hi only
__device__ __half g_wt[4u*DMODEL*DMODEL];      // W^T fp16 hi only; segs q,k,v,o
__device__ __half g_ao[(size_t)MTOT*2*DMODEL]; // attention out split (hi|lo)
__device__ __half g_qkvs[3*QKVPART];           // Qh,Kh,Vh [BH][S][64]
__device__ float g_biasc[3*DMODEL];            // concat bq*QSCALE|bk|bv

// ---------------------------------------------------------------------------
// PTX helpers (legal at virtual arch compute_103)
// ---------------------------------------------------------------------------
__device__ __forceinline__ uint32_t smem_u32(const void* p) {
    uint32_t a;
    asm("{ .reg .u64 t; cvta.to.shared.u64 t, %1; cvt.u32.u64 %0, t; }" : "=r"(a) : "l"(p));
    return a;
}

#define MBARRIER_INIT(addr, cnt) \
    asm volatile("mbarrier.init.shared.b64 [%0], %1;" :: "r"((uint32_t)(addr)), "r"((uint32_t)(cnt)) : "memory")
#define MBARRIER_EXPECT_TX(addr, bytes) \
    asm volatile("mbarrier.arrive.expect_tx.shared.b64 _, [%0], %1;" :: "r"((uint32_t)(addr)), "r"((uint32_t)(bytes)) : "memory")
#define MBARRIER_ARRIVE(addr) \
    asm volatile("mbarrier.arrive.release.cta.shared::cta.b64 _, [%0];" :: "r"((uint32_t)(addr)) : "memory")

#define MBARRIER_WAIT_PARITY(mbar_smem_addr, phase_parity) do { \
    uint32_t _mbar = (uint32_t)(mbar_smem_addr); \
    uint32_t _parity = (uint32_t)(phase_parity); \
    uint32_t _done; \
    asm volatile( \
        "{\n\t.reg .pred p;\n\t" \
        "mbarrier.try_wait.parity.acquire.cta.shared::cta.b64 p, [%1], %2;\n\t" \
        "selp.b32 %0, 1, 0, p;\n\t}" \
        : "=r"(_done) : "r"(_mbar), "r"(_parity) : "memory"); \
    if (!_done) { \
        asm volatile( \
            "{\n\t.reg .pred P1;\n\t" \
            "WAIT_LOOP_%=:\n\t" \
            "mbarrier.try_wait.parity.acquire.cta.shared::cta.b64 P1, [%0], %1, 0x989680;\n\t" \
            "@P1 bra.uni WAIT_DONE_%=;\n\t" \
            "bra.uni WAIT_LOOP_%=;\n\t" \
            "WAIT_DONE_%=:\n\t}" \
            :: "r"(_mbar), "r"(_parity) : "memory"); \
    } \
} while(0)

__device__ __forceinline__ void tma2d(uint32_t dst, const CUtensorMap* m, int x, int y, uint32_t bar) {
    asm volatile(
        "cp.async.bulk.tensor.2d.shared::cta.global.tile.mbarrier::complete_tx::bytes "
        "[%0], [%1, {%2, %3}], [%4];"
        :: "r"(dst), "l"(m), "r"(x), "r"(y), "r"(bar) : "memory");
}

__device__ __forceinline__ void ldsm_x4(uint32_t& r0, uint32_t& r1, uint32_t& r2, uint32_t& r3,
                                        uint32_t addr) {
    asm volatile("ldmatrix.sync.aligned.m8n8.x4.shared.b16 {%0,%1,%2,%3}, [%4];"
                 : "=r"(r0), "=r"(r1), "=r"(r2), "=r"(r3) : "r"(addr));
}
__device__ __forceinline__ void ldsm_x4_t(uint32_t& r0, uint32_t& r1, uint32_t& r2, uint32_t& r3,
                                          uint32_t addr) {
    asm volatile("ldmatrix.sync.aligned.m8n8.x4.trans.shared.b16 {%0,%1,%2,%3}, [%4];"
                 : "=r"(r0), "=r"(r1), "=r"(r2), "=r"(r3) : "r"(addr));
}

// fp16 mma, fp32 accum
__device__ __forceinline__ void mma16816h(float* c, const uint32_t* a, uint32_t b0, uint32_t b1) {
    asm volatile(
        "mma.sync.aligned.m16n8k16.row.col.f32.f16.f16.f32 "
        "{%0,%1,%2,%3}, {%4,%5,%6,%7}, {%8,%9}, {%0,%1,%2,%3};"
        : "+f"(c[0]), "+f"(c[1]), "+f"(c[2]), "+f"(c[3])
        : "r"(a[0]), "r"(a[1]), "r"(a[2]), "r"(a[3]), "r"(b0), "r"(b1));
}

__device__ __forceinline__ uint32_t pack2_f16(float x0, float x1) {
    uint32_t u;
    asm("cvt.rn.f16x2.f32 %0, %1, %2;" : "=r"(u) : "f"(x1), "f"(x0));
    return u;
}
__device__ __forceinline__ void split_pack2_f16(float x0, float x1, uint32_t& hp, uint32_t& lp) {
    hp = pack2_f16(x0, x1);
    __half2 hh = *reinterpret_cast<__half2*>(&hp);
    lp = pack2_f16(x0 - __low2float(hh), x1 - __high2float(hh));
}
__device__ __forceinline__ float ex2(float x) {
    float y; asm("ex2.approx.f32 %0, %1;" : "=f"(y) : "f"(x)); return y;
}

// smem address for 16B unit `u` of row `r` in a SW128 tile (128B rows)
__device__ __forceinline__ uint32_t ldsm_addr(uint32_t base, int r, int u) {
    return base + (uint32_t)r * 128u + (uint32_t)((u ^ (r & 7)) << 4);
}

// ---------------------------------------------------------------------------
// Fused preprocessing
// ---------------------------------------------------------------------------
__global__ void __launch_bounds__(256)
split_rows_kernel(const float* __restrict__ q, const float* __restrict__ k,
                  const float* __restrict__ v, __half* __restrict__ dstbase)
{
    const float* x = (blockIdx.y == 0) ? q : (blockIdx.y == 1) ? k : v;
    __half* dst = dstbase + (size_t)blockIdx.y * MTOT * DMODEL;
    const int m = blockIdx.x;
    const int k4 = threadIdx.x * 4;
    float4 val = *(const float4*)&x[(size_t)m * DMODEL + k4];
    __half* hi = dst + (size_t)m * DMODEL + k4;
    *(uint32_t*)(hi)     = pack2_f16(val.x, val.y);
    *(uint32_t*)(hi + 2) = pack2_f16(val.z, val.w);
}

__global__ void __launch_bounds__(256)
wt_split_kernel(const float* __restrict__ Wq, const float* __restrict__ Wk,
                const float* __restrict__ Wv, const float* __restrict__ Wo,
                __half* __restrict__ Tbase)
{
    const float* W = (blockIdx.z == 0) ? Wq : (blockIdx.z == 1) ? Wk
                   : (blockIdx.z == 2) ? Wv : Wo;
    const float sc = (blockIdx.z == 0) ? QSCALE : 1.0f;
    __half* T = Tbase + (size_t)blockIdx.z * DMODEL * DMODEL;
    __shared__ float t[32][33];
    const int n0 = blockIdx.x * 32, k0 = blockIdx.y * 32;
    const int tx = threadIdx.x, ty = threadIdx.y;   // (32, 8)
#pragma unroll
    for (int i = 0; i < 4; i++)
        t[ty + 8*i][tx] = W[(size_t)(k0 + ty + 8*i) * DMODEL + n0 + tx];
    __syncthreads();
#pragma unroll
    for (int i = 0; i < 4; i++) {
        const int n = n0 + ty + 8*i;
        const int k = k0 + tx;
        T[(size_t)n * DMODEL + k] = __float2half(t[tx][ty + 8*i] * sc);
    }
}

__global__ void __launch_bounds__(256)
bias_concat_kernel(const float* __restrict__ bq, const float* __restrict__ bk,
                   const float* __restrict__ bv, float* __restrict__ dst)
{
    const int i = blockIdx.x * 256 + threadIdx.x;       // 0..3071
    const float* s = (i < 1024) ? bq : (i < 2048) ? bk : bv;
    const float sc = (i < 1024) ? QSCALE : 1.0f;
    dst[i] = s[i & 1023] * sc;
}

// ---------------------------------------------------------------------------
// fp16 HMMA GEMM core, K=1024.
// NPROD=1: C = Ah*Bh (3-stage, kk-level fragment double-buffering).
// NPROD=2: C = Ah*Bh + Al*Bh (2-stage).
// MODE 0: row-major fp32 C.  MODE 1: fp16 hi scatter to [BH][S][64].
// ---------------------------------------------------------------------------
#define BK       64
#define NCHUNK   16
#define GTILE    16384              // 128 rows x 128B
#define GSMEM    (1024 + 6*GTILE)

template<int MODE, int NPROD>
__device__ __forceinline__ void gemm_core(
    const CUtensorMap* tmA, const CUtensorMap* tmB,
    const float* __restrict__ bias, float* __restrict__ C,
    __half* __restrict__ Ohi, int bm, int bn)
{
    constexpr int NSTG = (NPROD == 1) ? 3 : 2;
    constexpr int SSZ  = (NPROD == 1) ? 2*GTILE : 3*GTILE;

    extern __shared__ char sm_raw[];
    const uint32_t sb = smem_u32(sm_raw);
    const uint32_t tiles = (sb + 1024) & ~1023u;
    const int tid = threadIdx.x;
    const int lane = tid & 31, wid = tid >> 5;
    const int wm = wid & 3, wn = wid >> 2;

    const uint32_t FULL = sb;            // 3 x 8B
    const uint32_t EMPTY = sb + 24;      // 3 x 8B

    if (tid == 0) {
#pragma unroll
        for (int s = 0; s < NSTG; s++) {
            MBARRIER_INIT(FULL + 8*s, 1);
            MBARRIER_INIT(EMPTY + 8*s, 8);
        }
    }
    __syncthreads();

    if (tid == 0) {
#pragma unroll
        for (int s = 0; s < NSTG; s++) {
            MBARRIER_EXPECT_TX(FULL + 8*s, SSZ);
            const uint32_t st = tiles + s*SSZ;
            if (NPROD == 1) {
                tma2d(st,         tmA, s*BK, bm, FULL + 8*s);
                tma2d(st + GTILE, tmB, s*BK, bn, FULL + 8*s);
            } else {
                tma2d(st,           tmA, s*BK,          bm, FULL + 8*s);
                tma2d(st + GTILE,   tmA, DMODEL + s*BK, bm, FULL + 8*s);
                tma2d(st + 2*GTILE, tmB, s*BK,          bn, FULL + 8*s);
            }
        }
    }

    float acc[2][8][4];
#pragma unroll
    for (int i = 0; i < 2; i++)
#pragma unroll
        for (int j = 0; j < 8; j++)
#pragma unroll
            for (int q = 0; q < 4; q++) acc[i][j][q] = 0.f;

    const int lrow = lane & 15;
    const int lcolhalf = lane >> 4;
    const int sw = lane & 7;

    for (int c = 0; c < NCHUNK; c++) {
        const int s = c % NSTG;
        const int ph = (c / NSTG) & 1;
        MBARRIER_WAIT_PARITY(FULL + 8*s, ph);

        const uint32_t Ah = tiles + s*SSZ;
        const uint32_t Al = Ah + GTILE;                       // NPROD==2 only
        const uint32_t Bs = Ah + (NPROD == 1 ? GTILE : 2*GTILE);

        if (NPROD == 1) {
            // kk-level fragment double-buffering
            uint32_t af[2][2][4], bf[2][4][4];
            {
                const uint32_t coff0 = (uint32_t)(((0 + lcolhalf) ^ sw) << 4);
#pragma unroll
                for (int mi = 0; mi < 2; mi++) {
                    const int r = wm*32 + mi*16 + lrow;
                    ldsm_x4(af[0][mi][0], af[0][mi][1], af[0][mi][2], af[0][mi][3],
                            Ah + (uint32_t)r*128 + coff0);
                }
#pragma unroll
                for (int ni = 0; ni < 4; ni++) {
                    const int r = wn*64 + ni*16 + lrow;
                    ldsm_x4(bf[0][ni][0], bf[0][ni][1], bf[0][ni][2], bf[0][ni][3],
                            Bs + (uint32_t)r*128 + coff0);
                }
            }
#pragma unroll
            for (int kk = 0; kk < 4; kk++) {
                const int cur = kk & 1, nxt = cur ^ 1;
                if (kk < 3) {
                    const uint32_t coffn = (uint32_t)(((2*(kk+1) + lcolhalf) ^ sw) << 4);
#pragma unroll
                    for (int mi = 0; mi < 2; mi++) {
                        const int r = wm*32 + mi*16 + lrow;
                        ldsm_x4(af[nxt][mi][0], af[nxt][mi][1], af[nxt][mi][2], af[nxt][mi][3],
                                Ah + (uint32_t)r*128 + coffn);
                    }
#pragma unroll
                    for (int ni = 0; ni < 4; ni++) {
                        const int r = wn*64 + ni*16 + lrow;
                        ldsm_x4(bf[nxt][ni][0], bf[nxt][ni][1], bf[nxt][ni][2], bf[nxt][ni][3],
                                Bs + (uint32_t)r*128 + coffn);
                    }
                }
#pragma unroll
                for (int mi = 0; mi < 2; mi++)
#pragma unroll
                    for (int ni = 0; ni < 4; ni++) {
                        mma16816h(acc[mi][2*ni+0], af[cur][mi], bf[cur][ni][0], bf[cur][ni][2]);
                        mma16816h(acc[mi][2*ni+1], af[cur][mi], bf[cur][ni][1], bf[cur][ni][3]);
                    }
            }
        } else {
#pragma unroll
            for (int kk = 0; kk < 4; kk++) {
                const int cidx = 2*kk + lcolhalf;
                const uint32_t coff = (uint32_t)((cidx ^ sw) << 4);
                uint32_t ah[2][4], al[2][4];
#pragma unroll
                for (int mi = 0; mi < 2; mi++) {
                    const int r = wm*32 + mi*16 + lrow;
                    ldsm_x4(ah[mi][0], ah[mi][1], ah[mi][2], ah[mi][3],
                            Ah + (uint32_t)r*128 + coff);
                    ldsm_x4(al[mi][0], al[mi][1], al[mi][2], al[mi][3],
                            Al + (uint32_t)r*128 + coff);
                }
                uint32_t b[4][4];
#pragma unroll
                for (int ni = 0; ni < 4; ni++) {
                    const int r = wn*64 + ni*16 + lrow;
                    ldsm_x4(b[ni][0], b[ni][1], b[ni][2], b[ni][3],
                            Bs + (uint32_t)r*128 + coff);
                }
#pragma unroll
                for (int mi = 0; mi < 2; mi++)
#pragma unroll
                    for (int ni = 0; ni < 4; ni++) {
                        mma16816h(acc[mi][2*ni+0], ah[mi], b[ni][0], b[ni][2]);
                        mma16816h(acc[mi][2*ni+1], ah[mi], b[ni][1], b[ni][3]);
                        mma16816h(acc[mi][2*ni+0], al[mi], b[ni][0], b[ni][2]);
                        mma16816h(acc[mi][2*ni+1], al[mi], b[ni][1], b[ni][3]);
                    }
            }
        }
        if (lane == 0) MBARRIER_ARRIVE(EMPTY + 8*s);
        if (tid == 0 && c + NSTG < NCHUNK) {
            MBARRIER_WAIT_PARITY(EMPTY + 8*s, ph);
            MBARRIER_EXPECT_TX(FULL + 8*s, SSZ);
            const int kx = (c + NSTG) * BK;
            if (NPROD == 1) {
                tma2d(Ah, tmA, kx, bm, FULL + 8*s);
                tma2d(Bs, tmB, kx, bn, FULL + 8*s);
            } else {
                tma2d(Ah, tmA, kx,          bm, FULL + 8*s);
                tma2d(Al, tmA, DMODEL + kx, bm, FULL + 8*s);
                tma2d(Bs, tmB, kx,          bn, FULL + 8*s);
            }
        }
    }

    const int grp = lane >> 2;
    const int qd  = lane & 3;
#pragma unroll
    for (int mi = 0; mi < 2; mi++) {
#pragma unroll
        for (int nj = 0; nj < 8; nj++) {
            const int col = bn + wn*64 + nj*8 + qd*2;
            const float b0 = __ldg(&bias[col]);
            const float b1 = __ldg(&bias[col + 1]);
#pragma unroll
            for (int half = 0; half < 2; half++) {
                const int m = bm + wm*32 + mi*16 + grp + half*8;
                const float v0 = acc[mi][nj][2*half+0] + b0;
                const float v1 = acc[mi][nj][2*half+1] + b1;
                if (MODE == 0) {
                    *(float2*)&C[(size_t)m * DMODEL + col] = make_float2(v0, v1);
                } else {
                    const int b = m >> 11, srow = m & 2047;
                    const int h = col >> 6, d = col & 63;
                    const size_t off = (((size_t)b * NHEAD + h) * SEQ + srow) * DHEAD + d;
                    *(uint32_t*)&Ohi[off] = pack2_f16(v0, v1);
                }
            }
        }
    }
}

// Fused QKV: grid.z selects tensor; 1-product.
struct QkvMaps { CUtensorMap a[3]; CUtensorMap b[3]; };

__global__ void __launch_bounds__(256, 2)
gemm_qkv(const __grid_constant__ QkvMaps maps,
         const float* __restrict__ biasc, __half* __restrict__ qkvbase)
{
    const int i = blockIdx.z;
    gemm_core<1, 1>(&maps.a[i], &maps.b[i], biasc + i * DMODEL, nullptr,
                    qkvbase + (size_t)i * QKVPART,
                    blockIdx.y * 128, blockIdx.x * 128);
}

__global__ void __launch_bounds__(256, 2)
gemm_out(const __grid_constant__ CUtensorMap tmA,
         const __grid_constant__ CUtensorMap tmB,
         const float* __restrict__ bias, float* __restrict__ C)
{
    gemm_core<0, 2>(&tmA, &tmB, bias, C, nullptr, blockIdx.y * 128, blockIdx.x * 128);
}

// ---------------------------------------------------------------------------
// Flash attention, pure fp16 HMMA, exp2 softmax. 3-stage KV pipeline,
// fragment double-buffered QK/PV loops. Output = split fp16 AO.
// ---------------------------------------------------------------------------
#define QT 128
#define KT 64
#define AT_TILEQ  16384
#define AT_TILEKV 8192
#define AT_STAGE  (2*AT_TILEKV)      // Kh, Vh
#define AT_NSTG   3
#define ASMEM (1024 + AT_TILEQ + AT_NSTG*AT_STAGE)
#define NKT   (SEQ / KT)

__global__ void __launch_bounds__(256, 2)
attn_mma(const __grid_constant__ CUtensorMap tmQ,
         const __grid_constant__ CUtensorMap tmK,
         const __grid_constant__ CUtensorMap tmV,
         __half* __restrict__ AO)
{
    extern __shared__ char smraw[];
    const uint32_t sb = smem_u32(smraw);
    const uint32_t tiles = (sb + 1024) & ~1023u;
    const uint32_t Qs = tiles;
    const uint32_t STG = tiles + AT_TILEQ;
    const int tid = threadIdx.x, lane = tid & 31, wid = tid >> 5;
    const int bh = blockIdx.y;
    const int q0 = blockIdx.x * QT;
    const int gy = bh * SEQ;

    const uint32_t BQ = sb, BF = sb + 8, BE = sb + 40;   // BF[3], BE[3]
    if (tid == 0) {
        MBARRIER_INIT(BQ, 1);
#pragma unroll
        for (int s = 0; s < AT_NSTG; s++) {
            MBARRIER_INIT(BF + 8*s, 1);
            MBARRIER_INIT(BE + 8*s, 8);
        }
    }
    __syncthreads();
    if (tid == 0) {
        MBARRIER_EXPECT_TX(BQ, AT_TILEQ);
        tma2d(Qs, &tmQ, 0, gy + q0, BQ);
#pragma unroll
        for (int s = 0; s < AT_NSTG; s++) {
            const uint32_t st = STG + s*AT_STAGE;
            MBARRIER_EXPECT_TX(BF + 8*s, AT_STAGE);
            tma2d(st,              &tmK, 0, gy + s*KT, BF + 8*s);
            tma2d(st + AT_TILEKV,  &tmV, 0, gy + s*KT, BF + 8*s);
        }
    }

    float m_run[2] = { -1e30f, -1e30f };
    float l_run[2] = { 0.f, 0.f };
    float o_acc[8][4];
#pragma unroll
    for (int i = 0; i < 8; i++)
#pragma unroll
        for (int j = 0; j < 4; j++) o_acc[i][j] = 0.f;

    MBARRIER_WAIT_PARITY(BQ, 0);

    const int r0q = wid * 16;
    const int la7 = lane & 7;
    const int g01 = (lane >> 3) & 1;
    const int g23 = lane >> 4;

    uint32_t qf[4][4];
#pragma unroll
    for (int j = 0; j < 4; j++) {
        const int rr = r0q + la7 + g01*8;
        const int uu = 2*j + g23;
        ldsm_x4(qf[j][0], qf[j][1], qf[j][2], qf[j][3], ldsm_addr(Qs, rr, uu));
    }

    const int rrK = la7 + g23*8;     // K ldsm row component
    const int rrV = la7 + g01*8;     // V ldsm row component

    for (int kt = 0; kt < NKT; kt++) {
        const int s = kt % AT_NSTG;
        const int ph = (kt / AT_NSTG) & 1;
        MBARRIER_WAIT_PARITY(BF + 8*s, ph);
        const uint32_t Kh = STG + s*AT_STAGE;
        const uint32_t Vh = Kh + AT_TILEKV;

        float sf[8][4];
#pragma unroll
        for (int i = 0; i < 8; i++)
#pragma unroll
            for (int j = 0; j < 4; j++) sf[i][j] = 0.f;

        // ---- S = Q K^T, flattened (j,np) loop, double-buffered K frags ----
        {
            uint32_t kb[2][4];
            ldsm_x4(kb[0][0], kb[0][1], kb[0][2], kb[0][3],
                    ldsm_addr(Kh, rrK, g01));           // t=0: j=0, np=0
#pragma unroll
            for (int t = 0; t < 16; t++) {
                const int j = t >> 2, np = t & 3;
                const int cur = t & 1, nxt = cur ^ 1;
                if (t < 15) {
                    const int tn = t + 1;
                    const int jn = tn >> 2, npn = tn & 3;
                    ldsm_x4(kb[nxt][0], kb[nxt][1], kb[nxt][2], kb[nxt][3],
                            ldsm_addr(Kh, npn*16 + rrK, 2*jn + g01));
                }
                mma16816h(sf[2*np+0], qf[j], kb[cur][0], kb[cur][1]);
                mma16816h(sf[2*np+1], qf[j], kb[cur][2], kb[cur][3]);
            }
        }

        // ---- online softmax in exp2 domain ----
#pragma unroll
        for (int hf = 0; hf < 2; hf++) {
            float mx = -1e30f;
#pragma unroll
            for (int nt = 0; nt < 8; nt++)
                mx = fmaxf(mx, fmaxf(sf[nt][2*hf], sf[nt][2*hf+1]));
            mx = fmaxf(mx, __shfl_xor_sync(0xffffffffu, mx, 1));
            mx = fmaxf(mx, __shfl_xor_sync(0xffffffffu, mx, 2));
            const float mnew = fmaxf(m_run[hf], mx);
            const float corr = ex2(m_run[hf] - mnew);
            float sum = 0.f;
#pragma unroll
            for (int nt = 0; nt < 8; nt++) {
                const float p0 = ex2(sf[nt][2*hf]   - mnew);
                const float p1 = ex2(sf[nt][2*hf+1] - mnew);
                sf[nt][2*hf] = p0; sf[nt][2*hf+1] = p1;
                sum += p0 + p1;
            }
            sum += __shfl_xor_sync(0xffffffffu, sum, 1);
            sum += __shfl_xor_sync(0xffffffffu, sum, 2);
            l_run[hf] = l_run[hf] * corr + sum;
            m_run[hf] = mnew;
#pragma unroll
            for (int nt = 0; nt < 8; nt++) {
                o_acc[nt][2*hf]   *= corr;
                o_acc[nt][2*hf+1] *= corr;
            }
        }

        // ---- O += P V, flattened (j,np) loop, double-buffered V frags ----
        {
            uint32_t vb[2][4];
            ldsm_x4_t(vb[0][0], vb[0][1], vb[0][2], vb[0][3],
                      ldsm_addr(Vh, rrV, g23));         // t=0: j=0, np=0
            uint32_t ph16[4];
#pragma unroll
            for (int t = 0; t < 16; t++) {
                const int j = t >> 2, np = t & 3;
                const int cur = t & 1, nxt = cur ^ 1;
                if ((t & 3) == 0) {
#pragma unroll
                    for (int u = 0; u < 4; u++) {
                        const int nt = 2*j + (u >> 1);
                        const int vv = (u & 1) * 2;
                        ph16[u] = pack2_f16(sf[nt][vv+0], sf[nt][vv+1]);
                    }
                }
                if (t < 15) {
                    const int tn = t + 1;
                    const int jn = tn >> 2, npn = tn & 3;
                    ldsm_x4_t(vb[nxt][0], vb[nxt][1], vb[nxt][2], vb[nxt][3],
                              ldsm_addr(Vh, 16*jn + rrV, 2*npn + g23));
                }
                mma16816h(o_acc[2*np+0], ph16, vb[cur][0], vb[cur][1]);
                mma16816h(o_acc[2*np+1], ph16, vb[cur][2], vb[cur][3]);
            }
        }

        if (lane == 0) MBARRIER_ARRIVE(BE + 8*s);
        if (tid == 0 && kt + AT_NSTG < NKT) {
            MBARRIER_WAIT_PARITY(BE + 8*s, ph);
            const uint32_t st = STG + s*AT_STAGE;
            MBARRIER_EXPECT_TX(BF + 8*s, AT_STAGE);
            tma2d(st,             &tmK, 0, gy + (kt+AT_NSTG)*KT, BF + 8*s);
            tma2d(st + AT_TILEKV, &tmV, 0, gy + (kt+AT_NSTG)*KT, BF + 8*s);
        }
    }

    const int b = bh >> 4, h = bh & 15;
#pragma unroll
    for (int hf = 0; hf < 2; hf++) {
        const float inv = 1.f / l_run[hf];
        const int srow = q0 + r0q + (lane >> 2) + hf*8;
#pragma unroll
        for (int nt = 0; nt < 8; nt++) {
            const int d = nt*8 + (lane & 3)*2;
            const float f0 = o_acc[nt][2*hf]   * inv;
            const float f1 = o_acc[nt][2*hf+1] * inv;
            uint32_t hp, lp;
            split_pack2_f16(f0, f1, hp, lp);
            const size_t base = ((size_t)b * SEQ + srow) * 2 * DMODEL + h * DHEAD + d;
            *(uint32_t*)&AO[base]          = hp;
            *(uint32_t*)&AO[base + DMODEL] = lp;
        }
    }
}

// ---------------------------------------------------------------------------
// Host
// ---------------------------------------------------------------------------
typedef CUresult (*PFN_tmEncode)(CUtensorMap*, CUtensorMapDataType, cuuint32_t, void*,
                                 const cuuint64_t*, const cuuint64_t*, const cuuint32_t*,
                                 const cuuint32_t*, CUtensorMapInterleave, CUtensorMapSwizzle,
                                 CUtensorMapL2promotion, CUtensorMapFloatOOBfill);

static void make_map(PFN_tmEncode enc, CUtensorMap* m, void* p, uint64_t rows,
                     uint64_t width, uint32_t b0, uint32_t b1)
{
    cuuint64_t dims[2]    = { width, rows };
    cuuint64_t strides[1] = { width * 2 };
    cuuint32_t box[2]     = { b0, b1 };
    cuuint32_t es[2]      = { 1, 1 };
    enc(m, CU_TENSOR_MAP_DATA_TYPE_FLOAT16, 2, p, dims, strides, box, es,
        CU_TENSOR_MAP_INTERLEAVE_NONE, CU_TENSOR_MAP_SWIZZLE_128B,
        CU_TENSOR_MAP_L2_PROMOTION_L2_128B, CU_TENSOR_MAP_FLOAT_OOB_FILL_NONE);
}

extern "C" void kernel_launch(void* const* d_in, const int* in_sizes, int n_in,
                              void* d_out, int out_size)
{
    const float* act[3] = { (const float*)d_in[0], (const float*)d_in[1], (const float*)d_in[2] };
    const float* W[4]   = { (const float*)d_in[3], (const float*)d_in[5], (const float*)d_in[7], (const float*)d_in[9] };
    const float* bia[4] = { (const float*)d_in[4], (const float*)d_in[6], (const float*)d_in[8], (const float*)d_in[10] };
    float* out = (float*)d_out;

    __half *pact, *pwt, *pao, *pqkv;
    float* pbc;
    cudaGetSymbolAddress((void**)&pact, g_act);
    cudaGetSymbolAddress((void**)&pwt,  g_wt);
    cudaGetSymbolAddress((void**)&pao,  g_ao);
    cudaGetSymbolAddress((void**)&pqkv, g_qkvs);
    cudaGetSymbolAddress((void**)&pbc,  g_biasc);

    PFN_tmEncode enc = nullptr;
    cudaDriverEntryPointQueryResult qr;
    cudaGetDriverEntryPointByVersion("cuTensorMapEncodeTiled", (void**)&enc, 12000,
                                     cudaEnableDefault, &qr);

    const size_t WM = (size_t)DMODEL * DMODEL;

    static QkvMaps qkvmaps;
    static CUtensorMap mAao, mBo, mQKV[3];
    for (int i = 0; i < 3; i++) {
        make_map(enc, &qkvmaps.a[i], pact + (size_t)i * MTOT * DMODEL, MTOT, DMODEL, BK, 128);
        make_map(enc, &qkvmaps.b[i], pwt + (size_t)i * WM, DMODEL, DMODEL, BK, 128);
    }
    make_map(enc, &mAao, pao, MTOT, 2*DMODEL, BK, 128);
    make_map(enc, &mBo, pwt + 3*WM, DMODEL, DMODEL, BK, 128);
    for (int i = 0; i < 3; i++)
        make_map(enc, &mQKV[i], pqkv + i * QKVPART, (uint64_t)BHTOT * SEQ, DHEAD,
                 DHEAD, (i == 0) ? QT : KT);

    cudaFuncSetAttribute(gemm_qkv, cudaFuncAttributeMaxDynamicSharedMemorySize, GSMEM);
    cudaFuncSetAttribute(gemm_out, cudaFuncAttributeMaxDynamicSharedMemorySize, GSMEM);
    cudaFuncSetAttribute(attn_mma, cudaFuncAttributeMaxDynamicSharedMemorySize, ASMEM);

    // 1. fused preprocessing
    split_rows_kernel<<<dim3(MTOT, 3), 256>>>(act[0], act[1], act[2], pact);
    wt_split_kernel<<<dim3(32, 32, 4), dim3(32, 8)>>>(W[0], W[1], W[2], W[3], pwt);
    bias_concat_kernel<<<12, 256>>>(bia[0], bia[1], bia[2], pbc);

    // 2. fused QKV projections (1-product, one launch) -> fp16 Q,K,V
    gemm_qkv<<<dim3(DMODEL/128, MTOT/128, 3), 256, GSMEM>>>(qkvmaps, pbc, pqkv);

    // 3. attention (pure fp16 HMMA, 3-stage), writes split AO
    attn_mma<<<dim3(SEQ / QT, BHTOT), 256, ASMEM>>>(mQKV[0], mQKV[1], mQKV[2], pao);

    // 4. output projection (2-product on split AO)
    gemm_out<<<dim3(DMODEL/128, MTOT/128), 256, GSMEM>>>(mAao, mBo, bia[3], out);
}

// round 14
// speedup vs baseline: 1.0399x; 1.0399x over previous
#include <cuda_runtime.h>
#include <cuda.h>
#include <cuda_fp16.h>
#include <cstdint>

#define BATCH 2
#define SEQ   2048
#define DMODEL 1024
#define NHEAD 16
#define DHEAD 64
#define MTOT  (BATCH*SEQ)          // 4096
#define BHTOT (BATCH*NHEAD)        // 32
#define QKVPART ((size_t)BHTOT*SEQ*DHEAD)

// 0.125 * log2(e), folded into Wq/bq at preprocessing time.
#define QSCALE 0.1803368801111832f

// ---------------------------------------------------------------------------
// Device scratch
// ---------------------------------------------------------------------------
__device__ __half g_act[3u*MTOT*DMODEL];       // activations fp16 hi only
__device__ __half g_wt[4u*DMODEL*DMODEL];      // W^T fp16 hi only; segs q,k,v,o
__device__ __half g_ao[(size_t)MTOT*2*DMODEL]; // attention out split (hi|lo)
__device__ __half g_qkvs[3*QKVPART];           // Qh,Kh,Vh [BH][S][64]
__device__ float g_biasc[3*DMODEL];            // concat bq*QSCALE|bk|bv

// ---------------------------------------------------------------------------
// PTX helpers (legal at virtual arch compute_103)
// ---------------------------------------------------------------------------
__device__ __forceinline__ uint32_t smem_u32(const void* p) {
    uint32_t a;
    asm("{ .reg .u64 t; cvta.to.shared.u64 t, %1; cvt.u32.u64 %0, t; }" : "=r"(a) : "l"(p));
    return a;
}

#define MBARRIER_INIT(addr, cnt) \
    asm volatile("mbarrier.init.shared.b64 [%0], %1;" :: "r"((uint32_t)(addr)), "r"((uint32_t)(cnt)) : "memory")
#define MBARRIER_EXPECT_TX(addr, bytes) \
    asm volatile("mbarrier.arrive.expect_tx.shared.b64 _, [%0], %1;" :: "r"((uint32_t)(addr)), "r"((uint32_t)(bytes)) : "memory")
#define MBARRIER_ARRIVE(addr) \
    asm volatile("mbarrier.arrive.release.cta.shared::cta.b64 _, [%0];" :: "r"((uint32_t)(addr)) : "memory")

#define MBARRIER_WAIT_PARITY(mbar_smem_addr, phase_parity) do { \
    uint32_t _mbar = (uint32_t)(mbar_smem_addr); \
    uint32_t _parity = (uint32_t)(phase_parity); \
    uint32_t _done; \
    asm volatile( \
        "{\n\t.reg .pred p;\n\t" \
        "mbarrier.try_wait.parity.acquire.cta.shared::cta.b64 p, [%1], %2;\n\t" \
        "selp.b32 %0, 1, 0, p;\n\t}" \
        : "=r"(_done) : "r"(_mbar), "r"(_parity) : "memory"); \
    if (!_done) { \
        asm volatile( \
            "{\n\t.reg .pred P1;\n\t" \
            "WAIT_LOOP_%=:\n\t" \
            "mbarrier.try_wait.parity.acquire.cta.shared::cta.b64 P1, [%0], %1, 0x989680;\n\t" \
            "@P1 bra.uni WAIT_DONE_%=;\n\t" \
            "bra.uni WAIT_LOOP_%=;\n\t" \
            "WAIT_DONE_%=:\n\t}" \
            :: "r"(_mbar), "r"(_parity) : "memory"); \
    } \
} while(0)

__device__ __forceinline__ void tma2d(uint32_t dst, const CUtensorMap* m, int x, int y, uint32_t bar) {
    asm volatile(
        "cp.async.bulk.tensor.2d.shared::cta.global.tile.mbarrier::complete_tx::bytes "
        "[%0], [%1, {%2, %3}], [%4];"
        :: "r"(dst), "l"(m), "r"(x), "r"(y), "r"(bar) : "memory");
}

__device__ __forceinline__ void ldsm_x4(uint32_t& r0, uint32_t& r1, uint32_t& r2, uint32_t& r3,
                                        uint32_t addr) {
    asm volatile("ldmatrix.sync.aligned.m8n8.x4.shared.b16 {%0,%1,%2,%3}, [%4];"
                 : "=r"(r0), "=r"(r1), "=r"(r2), "=r"(r3) : "r"(addr));
}
__device__ __forceinline__ void ldsm_x4_t(uint32_t& r0, uint32_t& r1, uint32_t& r2, uint32_t& r3,
                                          uint32_t addr) {
    asm volatile("ldmatrix.sync.aligned.m8n8.x4.trans.shared.b16 {%0,%1,%2,%3}, [%4];"
                 : "=r"(r0), "=r"(r1), "=r"(r2), "=r"(r3) : "r"(addr));
}

// fp16 mma, fp32 accum
__device__ __forceinline__ void mma16816h(float* c, const uint32_t* a, uint32_t b0, uint32_t b1) {
    asm volatile(
        "mma.sync.aligned.m16n8k16.row.col.f32.f16.f16.f32 "
        "{%0,%1,%2,%3}, {%4,%5,%6,%7}, {%8,%9}, {%0,%1,%2,%3};"
        : "+f"(c[0]), "+f"(c[1]), "+f"(c[2]), "+f"(c[3])
        : "r"(a[0]), "r"(a[1]), "r"(a[2]), "r"(a[3]), "r"(b0), "r"(b1));
}

__device__ __forceinline__ uint32_t pack2_f16(float x0, float x1) {
    uint32_t u;
    asm("cvt.rn.f16x2.f32 %0, %1, %2;" : "=r"(u) : "f"(x1), "f"(x0));
    return u;
}
__device__ __forceinline__ void split_pack2_f16(float x0, float x1, uint32_t& hp, uint32_t& lp) {
    hp = pack2_f16(x0, x1);
    __half2 hh = *reinterpret_cast<__half2*>(&hp);
    lp = pack2_f16(x0 - __low2float(hh), x1 - __high2float(hh));
}
__device__ __forceinline__ float ex2(float x) {
    float y; asm("ex2.approx.f32 %0, %1;" : "=f"(y) : "f"(x)); return y;
}

// smem address for 16B unit `u` of row `r` in a SW128 tile (128B rows)
__device__ __forceinline__ uint32_t ldsm_addr(uint32_t base, int r, int u) {
    return base + (uint32_t)r * 128u + (uint32_t)((u ^ (r & 7)) << 4);
}

// ---------------------------------------------------------------------------
// Fused preprocessing: ONE launch.
//   blocks [0, 12288)      : activation fp32->fp16 (tensor = blk/4096, row = blk%4096)
//   blocks [12288, 16384)  : weight transpose+convert (which = (blk-12288)/1024)
//   blocks [16384, 16396)  : bias concat
// ---------------------------------------------------------------------------
#define PRE_SPLIT_BLKS 12288
#define PRE_WT_BLKS    4096
#define PRE_BIAS_BLKS  12
#define PRE_TOTAL (PRE_SPLIT_BLKS + PRE_WT_BLKS + PRE_BIAS_BLKS)

__global__ void __launch_bounds__(256)
pre_kernel(const float* __restrict__ q, const float* __restrict__ k,
           const float* __restrict__ v,
           const float* __restrict__ Wq, const float* __restrict__ Wk,
           const float* __restrict__ Wv, const float* __restrict__ Wo,
           const float* __restrict__ bq, const float* __restrict__ bk,
           const float* __restrict__ bv,
           __half* __restrict__ actbase, __half* __restrict__ Tbase,
           float* __restrict__ biasc)
{
    __shared__ float t[32][33];
    const int blk = blockIdx.x;
    const int tid = threadIdx.x;

    if (blk < PRE_SPLIT_BLKS) {
        const int which = blk >> 12;          // /4096
        const int m = blk & 4095;
        const float* x = (which == 0) ? q : (which == 1) ? k : v;
        __half* dst = actbase + (size_t)which * MTOT * DMODEL;
        const int k4 = tid * 4;
        float4 val = *(const float4*)&x[(size_t)m * DMODEL + k4];
        __half* hi = dst + (size_t)m * DMODEL + k4;
        *(uint32_t*)(hi)     = pack2_f16(val.x, val.y);
        *(uint32_t*)(hi + 2) = pack2_f16(val.z, val.w);
    } else if (blk < PRE_SPLIT_BLKS + PRE_WT_BLKS) {
        const int r = blk - PRE_SPLIT_BLKS;
        const int which = r >> 10;            // /1024
        const int rem = r & 1023;
        const float* W = (which == 0) ? Wq : (which == 1) ? Wk
                       : (which == 2) ? Wv : Wo;
        const float sc = (which == 0) ? QSCALE : 1.0f;
        __half* T = Tbase + (size_t)which * DMODEL * DMODEL;
        const int n0 = (rem & 31) * 32;
        const int k0 = (rem >> 5) * 32;
        const int tx = tid & 31, ty = tid >> 5;   // 32 x 8
#pragma unroll
        for (int i = 0; i < 4; i++)
            t[ty + 8*i][tx] = W[(size_t)(k0 + ty + 8*i) * DMODEL + n0 + tx];
        __syncthreads();
#pragma unroll
        for (int i = 0; i < 4; i++) {
            const int n = n0 + ty + 8*i;
            const int kk = k0 + tx;
            T[(size_t)n * DMODEL + kk] = __float2half(t[tx][ty + 8*i] * sc);
        }
    } else {
        const int i = (blk - PRE_SPLIT_BLKS - PRE_WT_BLKS) * 256 + tid;  // 0..3071
        const float* s = (i < 1024) ? bq : (i < 2048) ? bk : bv;
        const float sc = (i < 1024) ? QSCALE : 1.0f;
        biasc[i] = s[i & 1023] * sc;
    }
}

// ---------------------------------------------------------------------------
// fp16 HMMA GEMM core, K=1024 (R12 structure — ptxas-scheduled mainloop).
// NPROD=1: C = Ah*Bh (3-stage).  NPROD=2: C = Ah*Bh + Al*Bh (2-stage).
// MODE 0: row-major fp32 C.  MODE 1: fp16 hi scatter to [BH][S][64].
// ---------------------------------------------------------------------------
#define BK       64
#define NCHUNK   16
#define GTILE    16384              // 128 rows x 128B
#define GSMEM    (1024 + 6*GTILE)

template<int MODE, int NPROD>
__device__ __forceinline__ void gemm_core(
    const CUtensorMap* tmA, const CUtensorMap* tmB,
    const float* __restrict__ bias, float* __restrict__ C,
    __half* __restrict__ Ohi, int bm, int bn)
{
    constexpr int NSTG = (NPROD == 1) ? 3 : 2;
    constexpr int SSZ  = (NPROD == 1) ? 2*GTILE : 3*GTILE;

    extern __shared__ char sm_raw[];
    const uint32_t sb = smem_u32(sm_raw);
    const uint32_t tiles = (sb + 1024) & ~1023u;
    const int tid = threadIdx.x;
    const int lane = tid & 31, wid = tid >> 5;
    const int wm = wid & 3, wn = wid >> 2;

    const uint32_t FULL = sb;            // 3 x 8B
    const uint32_t EMPTY = sb + 24;      // 3 x 8B

    if (tid == 0) {
#pragma unroll
        for (int s = 0; s < NSTG; s++) {
            MBARRIER_INIT(FULL + 8*s, 1);
            MBARRIER_INIT(EMPTY + 8*s, 8);
        }
    }
    __syncthreads();

    if (tid == 0) {
#pragma unroll
        for (int s = 0; s < NSTG; s++) {
            MBARRIER_EXPECT_TX(FULL + 8*s, SSZ);
            const uint32_t st = tiles + s*SSZ;
            if (NPROD == 1) {
                tma2d(st,         tmA, s*BK, bm, FULL + 8*s);
                tma2d(st + GTILE, tmB, s*BK, bn, FULL + 8*s);
            } else {
                tma2d(st,           tmA, s*BK,          bm, FULL + 8*s);
                tma2d(st + GTILE,   tmA, DMODEL + s*BK, bm, FULL + 8*s);
                tma2d(st + 2*GTILE, tmB, s*BK,          bn, FULL + 8*s);
            }
        }
    }

    float acc[2][8][4];
#pragma unroll
    for (int i = 0; i < 2; i++)
#pragma unroll
        for (int j = 0; j < 8; j++)
#pragma unroll
            for (int q = 0; q < 4; q++) acc[i][j][q] = 0.f;

    const int lrow = lane & 15;
    const int lcolhalf = lane >> 4;
    const int sw = lane & 7;

    for (int c = 0; c < NCHUNK; c++) {
        const int s = c % NSTG;
        const int ph = (c / NSTG) & 1;
        MBARRIER_WAIT_PARITY(FULL + 8*s, ph);

        const uint32_t Ah = tiles + s*SSZ;
        const uint32_t Al = Ah + GTILE;                       // NPROD==2 only
        const uint32_t Bs = Ah + (NPROD == 1 ? GTILE : 2*GTILE);

#pragma unroll
        for (int kk = 0; kk < 4; kk++) {
            const int cidx = 2*kk + lcolhalf;
            const uint32_t coff = (uint32_t)((cidx ^ sw) << 4);

            uint32_t ah[2][4], al[2][4];
#pragma unroll
            for (int mi = 0; mi < 2; mi++) {
                const int r = wm*32 + mi*16 + lrow;
                ldsm_x4(ah[mi][0], ah[mi][1], ah[mi][2], ah[mi][3],
                        Ah + (uint32_t)r*128 + coff);
                if (NPROD == 2)
                    ldsm_x4(al[mi][0], al[mi][1], al[mi][2], al[mi][3],
                            Al + (uint32_t)r*128 + coff);
            }
            uint32_t b[4][4];
#pragma unroll
            for (int ni = 0; ni < 4; ni++) {
                const int r = wn*64 + ni*16 + lrow;
                ldsm_x4(b[ni][0], b[ni][1], b[ni][2], b[ni][3],
                        Bs + (uint32_t)r*128 + coff);
            }
#pragma unroll
            for (int mi = 0; mi < 2; mi++)
#pragma unroll
                for (int ni = 0; ni < 4; ni++) {
                    mma16816h(acc[mi][2*ni+0], ah[mi], b[ni][0], b[ni][2]);
                    mma16816h(acc[mi][2*ni+1], ah[mi], b[ni][1], b[ni][3]);
                    if (NPROD == 2) {
                        mma16816h(acc[mi][2*ni+0], al[mi], b[ni][0], b[ni][2]);
                        mma16816h(acc[mi][2*ni+1], al[mi], b[ni][1], b[ni][3]);
                    }
                }
        }
        if (lane == 0) MBARRIER_ARRIVE(EMPTY + 8*s);
        if (tid == 0 && c + NSTG < NCHUNK) {
            MBARRIER_WAIT_PARITY(EMPTY + 8*s, ph);
            MBARRIER_EXPECT_TX(FULL + 8*s, SSZ);
            const int kx = (c + NSTG) * BK;
            if (NPROD == 1) {
                tma2d(Ah, tmA, kx, bm, FULL + 8*s);
                tma2d(Bs, tmB, kx, bn, FULL + 8*s);
            } else {
                tma2d(Ah, tmA, kx,          bm, FULL + 8*s);
                tma2d(Al, tmA, DMODEL + kx, bm, FULL + 8*s);
                tma2d(Bs, tmB, kx,          bn, FULL + 8*s);
            }
        }
    }

    const int grp = lane >> 2;
    const int qd  = lane & 3;
#pragma unroll
    for (int mi = 0; mi < 2; mi++) {
#pragma unroll
        for (int nj = 0; nj < 8; nj++) {
            const int col = bn + wn*64 + nj*8 + qd*2;
            const float b0 = __ldg(&bias[col]);
            const float b1 = __ldg(&bias[col + 1]);
#pragma unroll
            for (int half = 0; half < 2; half++) {
                const int m = bm + wm*32 + mi*16 + grp + half*8;
                const float v0 = acc[mi][nj][2*half+0] + b0;
                const float v1 = acc[mi][nj][2*half+1] + b1;
                if (MODE == 0) {
                    *(float2*)&C[(size_t)m * DMODEL + col] = make_float2(v0, v1);
                } else {
                    const int b = m >> 11, srow = m & 2047;
                    const int h = col >> 6, d = col & 63;
                    const size_t off = (((size_t)b * NHEAD + h) * SEQ + srow) * DHEAD + d;
                    *(uint32_t*)&Ohi[off] = pack2_f16(v0, v1);
                }
            }
        }
    }
}

// Fused QKV: grid.z selects tensor; 1-product.
struct QkvMaps { CUtensorMap a[3]; CUtensorMap b[3]; };

__global__ void __launch_bounds__(256, 2)
gemm_qkv(const __grid_constant__ QkvMaps maps,
         const float* __restrict__ biasc, __half* __restrict__ qkvbase)
{
    const int i = blockIdx.z;
    gemm_core<1, 1>(&maps.a[i], &maps.b[i], biasc + i * DMODEL, nullptr,
                    qkvbase + (size_t)i * QKVPART,
                    blockIdx.y * 128, blockIdx.x * 128);
}

__global__ void __launch_bounds__(256, 2)
gemm_out(const __grid_constant__ CUtensorMap tmA,
         const __grid_constant__ CUtensorMap tmB,
         const float* __restrict__ bias, float* __restrict__ C)
{
    gemm_core<0, 2>(&tmA, &tmB, bias, C, nullptr, blockIdx.y * 128, blockIdx.x * 128);
}

// ---------------------------------------------------------------------------
// Flash attention, pure fp16 HMMA, exp2 softmax (R12 structure).
// ---------------------------------------------------------------------------
#define QT 128
#define KT 64
#define AT_TILEQ  16384
#define AT_TILEKV 8192
#define AT_STAGE  (2*AT_TILEKV)      // Kh, Vh
#define ASMEM (1024 + AT_TILEQ + 2*AT_STAGE)

__global__ void __launch_bounds__(256, 2)
attn_mma(const __grid_constant__ CUtensorMap tmQ,
         const __grid_constant__ CUtensorMap tmK,
         const __grid_constant__ CUtensorMap tmV,
         __half* __restrict__ AO)
{
    extern __shared__ char smraw[];
    const uint32_t sb = smem_u32(smraw);
    const uint32_t tiles = (sb + 1024) & ~1023u;
    const uint32_t Qs = tiles;
    const uint32_t STG = tiles + AT_TILEQ;
    const int tid = threadIdx.x, lane = tid & 31, wid = tid >> 5;
    const int bh = blockIdx.y;
    const int q0 = blockIdx.x * QT;
    const int gy = bh * SEQ;

    const uint32_t BQ = sb, BF = sb + 8, BE = sb + 24;
    if (tid == 0) {
        MBARRIER_INIT(BQ, 1);
        MBARRIER_INIT(BF + 0, 1);
        MBARRIER_INIT(BF + 8, 1);
        MBARRIER_INIT(BE + 0, 8);
        MBARRIER_INIT(BE + 8, 8);
    }
    __syncthreads();
    if (tid == 0) {
        MBARRIER_EXPECT_TX(BQ, AT_TILEQ);
        tma2d(Qs, &tmQ, 0, gy + q0, BQ);
#pragma unroll
        for (int s = 0; s < 2; s++) {
            const uint32_t st = STG + s*AT_STAGE;
            MBARRIER_EXPECT_TX(BF + 8*s, AT_STAGE);
            tma2d(st,              &tmK, 0, gy + s*KT, BF + 8*s);
            tma2d(st + AT_TILEKV,  &tmV, 0, gy + s*KT, BF + 8*s);
        }
    }

    float m_run[2] = { -1e30f, -1e30f };
    float l_run[2] = { 0.f, 0.f };
    float o_acc[8][4];
#pragma unroll
    for (int i = 0; i < 8; i++)
#pragma unroll
        for (int j = 0; j < 4; j++) o_acc[i][j] = 0.f;

    MBARRIER_WAIT_PARITY(BQ, 0);

    const int r0q = wid * 16;
    const int la7 = lane & 7;
    const int g01 = (lane >> 3) & 1;
    const int g23 = lane >> 4;

    uint32_t qf[4][4];
#pragma unroll
    for (int j = 0; j < 4; j++) {
        const int rr = r0q + la7 + g01*8;
        const int uu = 2*j + g23;
        ldsm_x4(qf[j][0], qf[j][1], qf[j][2], qf[j][3], ldsm_addr(Qs, rr, uu));
    }

    for (int kt = 0; kt < SEQ / KT; kt++) {
        const int s = kt & 1, ph = (kt >> 1) & 1;
        MBARRIER_WAIT_PARITY(BF + 8*s, ph);
        const uint32_t Kh = STG + s*AT_STAGE;
        const uint32_t Vh = Kh + AT_TILEKV;

        float sf[8][4];
#pragma unroll
        for (int i = 0; i < 8; i++)
#pragma unroll
            for (int j = 0; j < 4; j++) sf[i][j] = 0.f;

#pragma unroll
        for (int j = 0; j < 4; j++) {
#pragma unroll
            for (int np = 0; np < 4; np++) {
                const int rr = np*16 + la7 + g23*8;
                const int uu = 2*j + g01;
                uint32_t k0,k1,k2,k3;
                ldsm_x4(k0,k1,k2,k3, ldsm_addr(Kh, rr, uu));
                mma16816h(sf[2*np+0], qf[j], k0, k1);
                mma16816h(sf[2*np+1], qf[j], k2, k3);
            }
        }

#pragma unroll
        for (int hf = 0; hf < 2; hf++) {
            float mx = -1e30f;
#pragma unroll
            for (int nt = 0; nt < 8; nt++)
                mx = fmaxf(mx, fmaxf(sf[nt][2*hf], sf[nt][2*hf+1]));
            mx = fmaxf(mx, __shfl_xor_sync(0xffffffffu, mx, 1));
            mx = fmaxf(mx, __shfl_xor_sync(0xffffffffu, mx, 2));
            const float mnew = fmaxf(m_run[hf], mx);
            const float corr = ex2(m_run[hf] - mnew);
            float sum = 0.f;
#pragma unroll
            for (int nt = 0; nt < 8; nt++) {
                const float p0 = ex2(sf[nt][2*hf]   - mnew);
                const float p1 = ex2(sf[nt][2*hf+1] - mnew);
                sf[nt][2*hf] = p0; sf[nt][2*hf+1] = p1;
                sum += p0 + p1;
            }
            sum += __shfl_xor_sync(0xffffffffu, sum, 1);
            sum += __shfl_xor_sync(0xffffffffu, sum, 2);
            l_run[hf] = l_run[hf] * corr + sum;
            m_run[hf] = mnew;
#pragma unroll
            for (int nt = 0; nt < 8; nt++) {
                o_acc[nt][2*hf]   *= corr;
                o_acc[nt][2*hf+1] *= corr;
            }
        }

#pragma unroll
        for (int j = 0; j < 4; j++) {
            uint32_t ph16[4];
#pragma unroll
            for (int t = 0; t < 4; t++) {
                const int nt = 2*j + (t >> 1);
                const int vv = (t & 1) * 2;
                ph16[t] = pack2_f16(sf[nt][vv+0], sf[nt][vv+1]);
            }
#pragma unroll
            for (int np = 0; np < 4; np++) {
                const int rr = 16*j + la7 + g01*8;
                const int uu = 2*np + g23;
                uint32_t v0,v1,v2,v3;
                ldsm_x4_t(v0,v1,v2,v3, ldsm_addr(Vh, rr, uu));
                mma16816h(o_acc[2*np+0], ph16, v0, v1);
                mma16816h(o_acc[2*np+1], ph16, v2, v3);
            }
        }

        if (lane == 0) MBARRIER_ARRIVE(BE + 8*s);
        if (tid == 0 && kt + 2 < SEQ / KT) {
            MBARRIER_WAIT_PARITY(BE + 8*s, ph);
            const uint32_t st = STG + s*AT_STAGE;
            MBARRIER_EXPECT_TX(BF + 8*s, AT_STAGE);
            tma2d(st,             &tmK, 0, gy + (kt+2)*KT, BF + 8*s);
            tma2d(st + AT_TILEKV, &tmV, 0, gy + (kt+2)*KT, BF + 8*s);
        }
    }

    const int b = bh >> 4, h = bh & 15;
#pragma unroll
    for (int hf = 0; hf < 2; hf++) {
        const float inv = 1.f / l_run[hf];
        const int srow = q0 + r0q + (lane >> 2) + hf*8;
#pragma unroll
        for (int nt = 0; nt < 8; nt++) {
            const int d = nt*8 + (lane & 3)*2;
            const float f0 = o_acc[nt][2*hf]   * inv;
            const float f1 = o_acc[nt][2*hf+1] * inv;
            uint32_t hp, lp;
            split_pack2_f16(f0, f1, hp, lp);
            const size_t base = ((size_t)b * SEQ + srow) * 2 * DMODEL + h * DHEAD + d;
            *(uint32_t*)&AO[base]          = hp;
            *(uint32_t*)&AO[base + DMODEL] = lp;
        }
    }
}

// ---------------------------------------------------------------------------
// Host
// ---------------------------------------------------------------------------
typedef CUresult (*PFN_tmEncode)(CUtensorMap*, CUtensorMapDataType, cuuint32_t, void*,
                                 const cuuint64_t*, const cuuint64_t*, const cuuint32_t*,
                                 const cuuint32_t*, CUtensorMapInterleave, CUtensorMapSwizzle,
                                 CUtensorMapL2promotion, CUtensorMapFloatOOBfill);

static void make_map(PFN_tmEncode enc, CUtensorMap* m, void* p, uint64_t rows,
                     uint64_t width, uint32_t b0, uint32_t b1)
{
    cuuint64_t dims[2]    = { width, rows };
    cuuint64_t strides[1] = { width * 2 };
    cuuint32_t box[2]     = { b0, b1 };
    cuuint32_t es[2]      = { 1, 1 };
    enc(m, CU_TENSOR_MAP_DATA_TYPE_FLOAT16, 2, p, dims, strides, box, es,
        CU_TENSOR_MAP_INTERLEAVE_NONE, CU_TENSOR_MAP_SWIZZLE_128B,
        CU_TENSOR_MAP_L2_PROMOTION_L2_128B, CU_TENSOR_MAP_FLOAT_OOB_FILL_NONE);
}

extern "C" void kernel_launch(void* const* d_in, const int* in_sizes, int n_in,
                              void* d_out, int out_size)
{
    const float* act[3] = { (const float*)d_in[0], (const float*)d_in[1], (const float*)d_in[2] };
    const float* W[4]   = { (const float*)d_in[3], (const float*)d_in[5], (const float*)d_in[7], (const float*)d_in[9] };
    const float* bia[4] = { (const float*)d_in[4], (const float*)d_in[6], (const float*)d_in[8], (const float*)d_in[10] };
    float* out = (float*)d_out;

    __half *pact, *pwt, *pao, *pqkv;
    float* pbc;
    cudaGetSymbolAddress((void**)&pact, g_act);
    cudaGetSymbolAddress((void**)&pwt,  g_wt);
    cudaGetSymbolAddress((void**)&pao,  g_ao);
    cudaGetSymbolAddress((void**)&pqkv, g_qkvs);
    cudaGetSymbolAddress((void**)&pbc,  g_biasc);

    PFN_tmEncode enc = nullptr;
    cudaDriverEntryPointQueryResult qr;
    cudaGetDriverEntryPointByVersion("cuTensorMapEncodeTiled", (void**)&enc, 12000,
                                     cudaEnableDefault, &qr);

    const size_t WM = (size_t)DMODEL * DMODEL;

    static QkvMaps qkvmaps;
    static CUtensorMap mAao, mBo, mQKV[3];
    for (int i = 0; i < 3; i++) {
        make_map(enc, &qkvmaps.a[i], pact + (size_t)i * MTOT * DMODEL, MTOT, DMODEL, BK, 128);
        make_map(enc, &qkvmaps.b[i], pwt + (size_t)i * WM, DMODEL, DMODEL, BK, 128);
    }
    make_map(enc, &mAao, pao, MTOT, 2*DMODEL, BK, 128);
    make_map(enc, &mBo, pwt + 3*WM, DMODEL, DMODEL, BK, 128);
    for (int i = 0; i < 3; i++)
        make_map(enc, &mQKV[i], pqkv + i * QKVPART, (uint64_t)BHTOT * SEQ, DHEAD,
                 DHEAD, (i == 0) ? QT : KT);

    cudaFuncSetAttribute(gemm_qkv, cudaFuncAttributeMaxDynamicSharedMemorySize, GSMEM);
    cudaFuncSetAttribute(gemm_out, cudaFuncAttributeMaxDynamicSharedMemorySize, GSMEM);
    cudaFuncSetAttribute(attn_mma, cudaFuncAttributeMaxDynamicSharedMemorySize, ASMEM);

    // 1. fused preprocessing (ONE launch)
    pre_kernel<<<PRE_TOTAL, 256>>>(act[0], act[1], act[2],
                                   W[0], W[1], W[2], W[3],
                                   bia[0], bia[1], bia[2],
                                   pact, pwt, pbc);

    // 2. fused QKV projections (1-product, one launch) -> fp16 Q,K,V
    gemm_qkv<<<dim3(DMODEL/128, MTOT/128, 3), 256, GSMEM>>>(qkvmaps, pbc, pqkv);

    // 3. attention (pure fp16 HMMA), writes split AO
    attn_mma<<<dim3(SEQ / QT, BHTOT), 256, ASMEM>>>(mQKV[0], mQKV[1], mQKV[2], pao);

    // 4. output projection (2-product on split AO)
    gemm_out<<<dim3(DMODEL/128, MTOT/128), 256, GSMEM>>>(mAao, mBo, bia[3], out);
}

// round 15
// speedup vs baseline: 1.0561x; 1.0156x over previous
#include <cuda_runtime.h>
#include <cuda.h>
#include <cuda_fp16.h>
#include <cstdint>

#define BATCH 2
#define SEQ   2048
#define DMODEL 1024
#define NHEAD 16
#define DHEAD 64
#define MTOT  (BATCH*SEQ)          // 4096
#define BHTOT (BATCH*NHEAD)        // 32
#define QKVPART ((size_t)BHTOT*SEQ*DHEAD)

// 0.125 * log2(e), folded into Wq/bq at preprocessing time.
#define QSCALE 0.1803368801111832f

// ---------------------------------------------------------------------------
// Device scratch
// ---------------------------------------------------------------------------
__device__ __half g_act[3u*MTOT*DMODEL];       // activations fp16 hi only
__device__ __half g_wt[4u*DMODEL*DMODEL];      // W^T fp16 hi only; segs q,k,v,o
__device__ __half g_ao[(size_t)MTOT*2*DMODEL]; // attention out split (hi|lo)
__device__ __half g_qkvs[3*QKVPART];           // Qh,Kh,Vh [BH][S][64]
__device__ float g_biasc[3*DMODEL];            // concat bq*QSCALE|bk|bv

// ---------------------------------------------------------------------------
// PTX helpers (legal at virtual arch compute_103)
// ---------------------------------------------------------------------------
__device__ __forceinline__ uint32_t smem_u32(const void* p) {
    uint32_t a;
    asm("{ .reg .u64 t; cvta.to.shared.u64 t, %1; cvt.u32.u64 %0, t; }" : "=r"(a) : "l"(p));
    return a;
}

#define MBARRIER_INIT(addr, cnt) \
    asm volatile("mbarrier.init.shared.b64 [%0], %1;" :: "r"((uint32_t)(addr)), "r"((uint32_t)(cnt)) : "memory")
#define MBARRIER_EXPECT_TX(addr, bytes) \
    asm volatile("mbarrier.arrive.expect_tx.shared.b64 _, [%0], %1;" :: "r"((uint32_t)(addr)), "r"((uint32_t)(bytes)) : "memory")
#define MBARRIER_ARRIVE(addr) \
    asm volatile("mbarrier.arrive.release.cta.shared::cta.b64 _, [%0];" :: "r"((uint32_t)(addr)) : "memory")

#define MBARRIER_WAIT_PARITY(mbar_smem_addr, phase_parity) do { \
    uint32_t _mbar = (uint32_t)(mbar_smem_addr); \
    uint32_t _parity = (uint32_t)(phase_parity); \
    uint32_t _done; \
    asm volatile( \
        "{\n\t.reg .pred p;\n\t" \
        "mbarrier.try_wait.parity.acquire.cta.shared::cta.b64 p, [%1], %2;\n\t" \
        "selp.b32 %0, 1, 0, p;\n\t}" \
        : "=r"(_done) : "r"(_mbar), "r"(_parity) : "memory"); \
    if (!_done) { \
        asm volatile( \
            "{\n\t.reg .pred P1;\n\t" \
            "WAIT_LOOP_%=:\n\t" \
            "mbarrier.try_wait.parity.acquire.cta.shared::cta.b64 P1, [%0], %1, 0x989680;\n\t" \
            "@P1 bra.uni WAIT_DONE_%=;\n\t" \
            "bra.uni WAIT_LOOP_%=;\n\t" \
            "WAIT_DONE_%=:\n\t}" \
            :: "r"(_mbar), "r"(_parity) : "memory"); \
    } \
} while(0)

__device__ __forceinline__ void tma2d(uint32_t dst, const CUtensorMap* m, int x, int y, uint32_t bar) {
    asm volatile(
        "cp.async.bulk.tensor.2d.shared::cta.global.tile.mbarrier::complete_tx::bytes "
        "[%0], [%1, {%2, %3}], [%4];"
        :: "r"(dst), "l"(m), "r"(x), "r"(y), "r"(bar) : "memory");
}

__device__ __forceinline__ void ldsm_x4(uint32_t& r0, uint32_t& r1, uint32_t& r2, uint32_t& r3,
                                        uint32_t addr) {
    asm volatile("ldmatrix.sync.aligned.m8n8.x4.shared.b16 {%0,%1,%2,%3}, [%4];"
                 : "=r"(r0), "=r"(r1), "=r"(r2), "=r"(r3) : "r"(addr));
}
__device__ __forceinline__ void ldsm_x4_t(uint32_t& r0, uint32_t& r1, uint32_t& r2, uint32_t& r3,
                                          uint32_t addr) {
    asm volatile("ldmatrix.sync.aligned.m8n8.x4.trans.shared.b16 {%0,%1,%2,%3}, [%4];"
                 : "=r"(r0), "=r"(r1), "=r"(r2), "=r"(r3) : "r"(addr));
}

// fp16 mma, fp32 accum
__device__ __forceinline__ void mma16816h(float* c, const uint32_t* a, uint32_t b0, uint32_t b1) {
    asm volatile(
        "mma.sync.aligned.m16n8k16.row.col.f32.f16.f16.f32 "
        "{%0,%1,%2,%3}, {%4,%5,%6,%7}, {%8,%9}, {%0,%1,%2,%3};"
        : "+f"(c[0]), "+f"(c[1]), "+f"(c[2]), "+f"(c[3])
        : "r"(a[0]), "r"(a[1]), "r"(a[2]), "r"(a[3]), "r"(b0), "r"(b1));
}

__device__ __forceinline__ uint32_t pack2_f16(float x0, float x1) {
    uint32_t u;
    asm("cvt.rn.f16x2.f32 %0, %1, %2;" : "=r"(u) : "f"(x1), "f"(x0));
    return u;
}
__device__ __forceinline__ void split_pack2_f16(float x0, float x1, uint32_t& hp, uint32_t& lp) {
    hp = pack2_f16(x0, x1);
    __half2 hh = *reinterpret_cast<__half2*>(&hp);
    lp = pack2_f16(x0 - __low2float(hh), x1 - __high2float(hh));
}
__device__ __forceinline__ float ex2(float x) {
    float y; asm("ex2.approx.f32 %0, %1;" : "=f"(y) : "f"(x)); return y;
}
__device__ __forceinline__ uint32_t ex2_f16x2(uint32_t x) {
    uint32_t y; asm("ex2.approx.f16x2 %0, %1;" : "=r"(y) : "r"(x)); return y;
}

// smem address for 16B unit `u` of row `r` in a SW128 tile (128B rows)
__device__ __forceinline__ uint32_t ldsm_addr(uint32_t base, int r, int u) {
    return base + (uint32_t)r * 128u + (uint32_t)((u ^ (r & 7)) << 4);
}

// ---------------------------------------------------------------------------
// Fused preprocessing: ONE launch.
// ---------------------------------------------------------------------------
#define PRE_SPLIT_BLKS 12288
#define PRE_WT_BLKS    4096
#define PRE_BIAS_BLKS  12
#define PRE_TOTAL (PRE_SPLIT_BLKS + PRE_WT_BLKS + PRE_BIAS_BLKS)

__global__ void __launch_bounds__(256)
pre_kernel(const float* __restrict__ q, const float* __restrict__ k,
           const float* __restrict__ v,
           const float* __restrict__ Wq, const float* __restrict__ Wk,
           const float* __restrict__ Wv, const float* __restrict__ Wo,
           const float* __restrict__ bq, const float* __restrict__ bk,
           const float* __restrict__ bv,
           __half* __restrict__ actbase, __half* __restrict__ Tbase,
           float* __restrict__ biasc)
{
    __shared__ float t[32][33];
    const int blk = blockIdx.x;
    const int tid = threadIdx.x;

    if (blk < PRE_SPLIT_BLKS) {
        const int which = blk >> 12;
        const int m = blk & 4095;
        const float* x = (which == 0) ? q : (which == 1) ? k : v;
        __half* dst = actbase + (size_t)which * MTOT * DMODEL;
        const int k4 = tid * 4;
        float4 val = *(const float4*)&x[(size_t)m * DMODEL + k4];
        __half* hi = dst + (size_t)m * DMODEL + k4;
        *(uint32_t*)(hi)     = pack2_f16(val.x, val.y);
        *(uint32_t*)(hi + 2) = pack2_f16(val.z, val.w);
    } else if (blk < PRE_SPLIT_BLKS + PRE_WT_BLKS) {
        const int r = blk - PRE_SPLIT_BLKS;
        const int which = r >> 10;
        const int rem = r & 1023;
        const float* W = (which == 0) ? Wq : (which == 1) ? Wk
                       : (which == 2) ? Wv : Wo;
        const float sc = (which == 0) ? QSCALE : 1.0f;
        __half* T = Tbase + (size_t)which * DMODEL * DMODEL;
        const int n0 = (rem & 31) * 32;
        const int k0 = (rem >> 5) * 32;
        const int tx = tid & 31, ty = tid >> 5;
#pragma unroll
        for (int i = 0; i < 4; i++)
            t[ty + 8*i][tx] = W[(size_t)(k0 + ty + 8*i) * DMODEL + n0 + tx];
        __syncthreads();
#pragma unroll
        for (int i = 0; i < 4; i++) {
            const int n = n0 + ty + 8*i;
            const int kk = k0 + tx;
            T[(size_t)n * DMODEL + kk] = __float2half(t[tx][ty + 8*i] * sc);
        }
    } else {
        const int i = (blk - PRE_SPLIT_BLKS - PRE_WT_BLKS) * 256 + tid;
        const float* s = (i < 1024) ? bq : (i < 2048) ? bk : bv;
        const float sc = (i < 1024) ? QSCALE : 1.0f;
        biasc[i] = s[i & 1023] * sc;
    }
}

// ---------------------------------------------------------------------------
// fp16 HMMA GEMM core, K=1024 (R14 structure).
// NPROD=1: C = Ah*Bh (3-stage).  NPROD=2: C = Ah*Bh + Al*Bh (2-stage).
// MODE 0: row-major fp32 C.  MODE 1: fp16 hi scatter to [BH][S][64].
// ---------------------------------------------------------------------------
#define BK       64
#define NCHUNK   16
#define GTILE    16384
#define GSMEM    (1024 + 6*GTILE)

template<int MODE, int NPROD>
__device__ __forceinline__ void gemm_core(
    const CUtensorMap* tmA, const CUtensorMap* tmB,
    const float* __restrict__ bias, float* __restrict__ C,
    __half* __restrict__ Ohi, int bm, int bn)
{
    constexpr int NSTG = (NPROD == 1) ? 3 : 2;
    constexpr int SSZ  = (NPROD == 1) ? 2*GTILE : 3*GTILE;

    extern __shared__ char sm_raw[];
    const uint32_t sb = smem_u32(sm_raw);
    const uint32_t tiles = (sb + 1024) & ~1023u;
    const int tid = threadIdx.x;
    const int lane = tid & 31, wid = tid >> 5;
    const int wm = wid & 3, wn = wid >> 2;

    const uint32_t FULL = sb;
    const uint32_t EMPTY = sb + 24;

    if (tid == 0) {
#pragma unroll
        for (int s = 0; s < NSTG; s++) {
            MBARRIER_INIT(FULL + 8*s, 1);
            MBARRIER_INIT(EMPTY + 8*s, 8);
        }
    }
    __syncthreads();

    if (tid == 0) {
#pragma unroll
        for (int s = 0; s < NSTG; s++) {
            MBARRIER_EXPECT_TX(FULL + 8*s, SSZ);
            const uint32_t st = tiles + s*SSZ;
            if (NPROD == 1) {
                tma2d(st,         tmA, s*BK, bm, FULL + 8*s);
                tma2d(st + GTILE, tmB, s*BK, bn, FULL + 8*s);
            } else {
                tma2d(st,           tmA, s*BK,          bm, FULL + 8*s);
                tma2d(st + GTILE,   tmA, DMODEL + s*BK, bm, FULL + 8*s);
                tma2d(st + 2*GTILE, tmB, s*BK,          bn, FULL + 8*s);
            }
        }
    }

    float acc[2][8][4];
#pragma unroll
    for (int i = 0; i < 2; i++)
#pragma unroll
        for (int j = 0; j < 8; j++)
#pragma unroll
            for (int q = 0; q < 4; q++) acc[i][j][q] = 0.f;

    const int lrow = lane & 15;
    const int lcolhalf = lane >> 4;
    const int sw = lane & 7;

    for (int c = 0; c < NCHUNK; c++) {
        const int s = c % NSTG;
        const int ph = (c / NSTG) & 1;
        MBARRIER_WAIT_PARITY(FULL + 8*s, ph);

        const uint32_t Ah = tiles + s*SSZ;
        const uint32_t Al = Ah + GTILE;
        const uint32_t Bs = Ah + (NPROD == 1 ? GTILE : 2*GTILE);

#pragma unroll
        for (int kk = 0; kk < 4; kk++) {
            const int cidx = 2*kk + lcolhalf;
            const uint32_t coff = (uint32_t)((cidx ^ sw) << 4);

            uint32_t ah[2][4], al[2][4];
#pragma unroll
            for (int mi = 0; mi < 2; mi++) {
                const int r = wm*32 + mi*16 + lrow;
                ldsm_x4(ah[mi][0], ah[mi][1], ah[mi][2], ah[mi][3],
                        Ah + (uint32_t)r*128 + coff);
                if (NPROD == 2)
                    ldsm_x4(al[mi][0], al[mi][1], al[mi][2], al[mi][3],
                            Al + (uint32_t)r*128 + coff);
            }
            uint32_t b[4][4];
#pragma unroll
            for (int ni = 0; ni < 4; ni++) {
                const int r = wn*64 + ni*16 + lrow;
                ldsm_x4(b[ni][0], b[ni][1], b[ni][2], b[ni][3],
                        Bs + (uint32_t)r*128 + coff);
            }
#pragma unroll
            for (int mi = 0; mi < 2; mi++)
#pragma unroll
                for (int ni = 0; ni < 4; ni++) {
                    mma16816h(acc[mi][2*ni+0], ah[mi], b[ni][0], b[ni][2]);
                    mma16816h(acc[mi][2*ni+1], ah[mi], b[ni][1], b[ni][3]);
                    if (NPROD == 2) {
                        mma16816h(acc[mi][2*ni+0], al[mi], b[ni][0], b[ni][2]);
                        mma16816h(acc[mi][2*ni+1], al[mi], b[ni][1], b[ni][3]);
                    }
                }
        }
        if (lane == 0) MBARRIER_ARRIVE(EMPTY + 8*s);
        if (tid == 0 && c + NSTG < NCHUNK) {
            MBARRIER_WAIT_PARITY(EMPTY + 8*s, ph);
            MBARRIER_EXPECT_TX(FULL + 8*s, SSZ);
            const int kx = (c + NSTG) * BK;
            if (NPROD == 1) {
                tma2d(Ah, tmA, kx, bm, FULL + 8*s);
                tma2d(Bs, tmB, kx, bn, FULL + 8*s);
            } else {
                tma2d(Ah, tmA, kx,          bm, FULL + 8*s);
                tma2d(Al, tmA, DMODEL + kx, bm, FULL + 8*s);
                tma2d(Bs, tmB, kx,          bn, FULL + 8*s);
            }
        }
    }

    const int grp = lane >> 2;
    const int qd  = lane & 3;
#pragma unroll
    for (int mi = 0; mi < 2; mi++) {
#pragma unroll
        for (int nj = 0; nj < 8; nj++) {
            const int col = bn + wn*64 + nj*8 + qd*2;
            const float b0 = __ldg(&bias[col]);
            const float b1 = __ldg(&bias[col + 1]);
#pragma unroll
            for (int half = 0; half < 2; half++) {
                const int m = bm + wm*32 + mi*16 + grp + half*8;
                const float v0 = acc[mi][nj][2*half+0] + b0;
                const float v1 = acc[mi][nj][2*half+1] + b1;
                if (MODE == 0) {
                    *(float2*)&C[(size_t)m * DMODEL + col] = make_float2(v0, v1);
                } else {
                    const int b = m >> 11, srow = m & 2047;
                    const int h = col >> 6, d = col & 63;
                    const size_t off = (((size_t)b * NHEAD + h) * SEQ + srow) * DHEAD + d;
                    *(uint32_t*)&Ohi[off] = pack2_f16(v0, v1);
                }
            }
        }
    }
}

struct QkvMaps { CUtensorMap a[3]; CUtensorMap b[3]; };

__global__ void __launch_bounds__(256, 2)
gemm_qkv(const __grid_constant__ QkvMaps maps,
         const float* __restrict__ biasc, __half* __restrict__ qkvbase)
{
    const int i = blockIdx.z;
    gemm_core<1, 1>(&maps.a[i], &maps.b[i], biasc + i * DMODEL, nullptr,
                    qkvbase + (size_t)i * QKVPART,
                    blockIdx.y * 128, blockIdx.x * 128);
}

__global__ void __launch_bounds__(256, 2)
gemm_out(const __grid_constant__ CUtensorMap tmA,
         const __grid_constant__ CUtensorMap tmB,
         const float* __restrict__ bias, float* __restrict__ C)
{
    gemm_core<0, 2>(&tmA, &tmB, bias, C, nullptr, blockIdx.y * 128, blockIdx.x * 128);
}

// ---------------------------------------------------------------------------
// Flash attention, pure fp16 HMMA, f16x2 exp2 softmax (halved MUFU load).
// ---------------------------------------------------------------------------
#define QT 128
#define KT 64
#define AT_TILEQ  16384
#define AT_TILEKV 8192
#define AT_STAGE  (2*AT_TILEKV)      // Kh, Vh
#define ASMEM (1024 + AT_TILEQ + 2*AT_STAGE)

__global__ void __launch_bounds__(256, 2)
attn_mma(const __grid_constant__ CUtensorMap tmQ,
         const __grid_constant__ CUtensorMap tmK,
         const __grid_constant__ CUtensorMap tmV,
         __half* __restrict__ AO)
{
    extern __shared__ char smraw[];
    const uint32_t sb = smem_u32(smraw);
    const uint32_t tiles = (sb + 1024) & ~1023u;
    const uint32_t Qs = tiles;
    const uint32_t STG = tiles + AT_TILEQ;
    const int tid = threadIdx.x, lane = tid & 31, wid = tid >> 5;
    const int bh = blockIdx.y;
    const int q0 = blockIdx.x * QT;
    const int gy = bh * SEQ;

    const uint32_t BQ = sb, BF = sb + 8, BE = sb + 24;
    if (tid == 0) {
        MBARRIER_INIT(BQ, 1);
        MBARRIER_INIT(BF + 0, 1);
        MBARRIER_INIT(BF + 8, 1);
        MBARRIER_INIT(BE + 0, 8);
        MBARRIER_INIT(BE + 8, 8);
    }
    __syncthreads();
    if (tid == 0) {
        MBARRIER_EXPECT_TX(BQ, AT_TILEQ);
        tma2d(Qs, &tmQ, 0, gy + q0, BQ);
#pragma unroll
        for (int s = 0; s < 2; s++) {
            const uint32_t st = STG + s*AT_STAGE;
            MBARRIER_EXPECT_TX(BF + 8*s, AT_STAGE);
            tma2d(st,              &tmK, 0, gy + s*KT, BF + 8*s);
            tma2d(st + AT_TILEKV,  &tmV, 0, gy + s*KT, BF + 8*s);
        }
    }

    float m_run[2] = { -1e30f, -1e30f };
    float l_run[2] = { 0.f, 0.f };
    float o_acc[8][4];
#pragma unroll
    for (int i = 0; i < 8; i++)
#pragma unroll
        for (int j = 0; j < 4; j++) o_acc[i][j] = 0.f;

    MBARRIER_WAIT_PARITY(BQ, 0);

    const int r0q = wid * 16;
    const int la7 = lane & 7;
    const int g01 = (lane >> 3) & 1;
    const int g23 = lane >> 4;

    uint32_t qf[4][4];
#pragma unroll
    for (int j = 0; j < 4; j++) {
        const int rr = r0q + la7 + g01*8;
        const int uu = 2*j + g23;
        ldsm_x4(qf[j][0], qf[j][1], qf[j][2], qf[j][3], ldsm_addr(Qs, rr, uu));
    }

    for (int kt = 0; kt < SEQ / KT; kt++) {
        const int s = kt & 1, ph = (kt >> 1) & 1;
        MBARRIER_WAIT_PARITY(BF + 8*s, ph);
        const uint32_t Kh = STG + s*AT_STAGE;
        const uint32_t Vh = Kh + AT_TILEKV;

        float sf[8][4];
#pragma unroll
        for (int i = 0; i < 8; i++)
#pragma unroll
            for (int j = 0; j < 4; j++) sf[i][j] = 0.f;

#pragma unroll
        for (int j = 0; j < 4; j++) {
#pragma unroll
            for (int np = 0; np < 4; np++) {
                const int rr = np*16 + la7 + g23*8;
                const int uu = 2*j + g01;
                uint32_t k0,k1,k2,k3;
                ldsm_x4(k0,k1,k2,k3, ldsm_addr(Kh, rr, uu));
                mma16816h(sf[2*np+0], qf[j], k0, k1);
                mma16816h(sf[2*np+1], qf[j], k2, k3);
            }
        }

        // ---- online softmax: exp2 computed in fp16x2 pairs (P fragments) ----
        uint32_t psf[8][2];   // psf[nt][hf] = fp16x2 (p0, p1) — PV A-fragments
#pragma unroll
        for (int hf = 0; hf < 2; hf++) {
            float mx = -1e30f;
#pragma unroll
            for (int nt = 0; nt < 8; nt++)
                mx = fmaxf(mx, fmaxf(sf[nt][2*hf], sf[nt][2*hf+1]));
            mx = fmaxf(mx, __shfl_xor_sync(0xffffffffu, mx, 1));
            mx = fmaxf(mx, __shfl_xor_sync(0xffffffffu, mx, 2));
            const float mnew = fmaxf(m_run[hf], mx);
            const float corr = ex2(m_run[hf] - mnew);
            float sum = 0.f;
#pragma unroll
            for (int nt = 0; nt < 8; nt++) {
                const uint32_t u = pack2_f16(sf[nt][2*hf] - mnew,
                                             sf[nt][2*hf+1] - mnew);
                const uint32_t p2 = ex2_f16x2(u);
                psf[nt][hf] = p2;
                const float2 pf = __half22float2(*reinterpret_cast<const __half2*>(&p2));
                sum += pf.x + pf.y;
            }
            sum += __shfl_xor_sync(0xffffffffu, sum, 1);
            sum += __shfl_xor_sync(0xffffffffu, sum, 2);
            l_run[hf] = l_run[hf] * corr + sum;
            m_run[hf] = mnew;
#pragma unroll
            for (int nt = 0; nt < 8; nt++) {
                o_acc[nt][2*hf]   *= corr;
                o_acc[nt][2*hf+1] *= corr;
            }
        }

        // ---- O += P V (P fragments come directly from the f16x2 exp2) ----
#pragma unroll
        for (int j = 0; j < 4; j++) {
            uint32_t ph16[4];
#pragma unroll
            for (int t = 0; t < 4; t++)
                ph16[t] = psf[2*j + (t >> 1)][t & 1];
#pragma unroll
            for (int np = 0; np < 4; np++) {
                const int rr = 16*j + la7 + g01*8;
                const int uu = 2*np + g23;
                uint32_t v0,v1,v2,v3;
                ldsm_x4_t(v0,v1,v2,v3, ldsm_addr(Vh, rr, uu));
                mma16816h(o_acc[2*np+0], ph16, v0, v1);
                mma16816h(o_acc[2*np+1], ph16, v2, v3);
            }
        }

        if (lane == 0) MBARRIER_ARRIVE(BE + 8*s);
        if (tid == 0 && kt + 2 < SEQ / KT) {
            MBARRIER_WAIT_PARITY(BE + 8*s, ph);
            const uint32_t st = STG + s*AT_STAGE;
            MBARRIER_EXPECT_TX(BF + 8*s, AT_STAGE);
            tma2d(st,             &tmK, 0, gy + (kt+2)*KT, BF + 8*s);
            tma2d(st + AT_TILEKV, &tmV, 0, gy + (kt+2)*KT, BF + 8*s);
        }
    }

    const int b = bh >> 4, h = bh & 15;
#pragma unroll
    for (int hf = 0; hf < 2; hf++) {
        const float inv = 1.f / l_run[hf];
        const int srow = q0 + r0q + (lane >> 2) + hf*8;
#pragma unroll
        for (int nt = 0; nt < 8; nt++) {
            const int d = nt*8 + (lane & 3)*2;
            const float f0 = o_acc[nt][2*hf]   * inv;
            const float f1 = o_acc[nt][2*hf+1] * inv;
            uint32_t hp, lp;
            split_pack2_f16(f0, f1, hp, lp);
            const size_t base = ((size_t)b * SEQ + srow) * 2 * DMODEL + h * DHEAD + d;
            *(uint32_t*)&AO[base]          = hp;
            *(uint32_t*)&AO[base + DMODEL] = lp;
        }
    }
}

// ---------------------------------------------------------------------------
// Host
// ---------------------------------------------------------------------------
typedef CUresult (*PFN_tmEncode)(CUtensorMap*, CUtensorMapDataType, cuuint32_t, void*,
                                 const cuuint64_t*, const cuuint64_t*, const cuuint32_t*,
                                 const cuuint32_t*, CUtensorMapInterleave, CUtensorMapSwizzle,
                                 CUtensorMapL2promotion, CUtensorMapFloatOOBfill);

static void make_map(PFN_tmEncode enc, CUtensorMap* m, void* p, uint64_t rows,
                     uint64_t width, uint32_t b0, uint32_t b1)
{
    cuuint64_t dims[2]    = { width, rows };
    cuuint64_t strides[1] = { width * 2 };
    cuuint32_t box[2]     = { b0, b1 };
    cuuint32_t es[2]      = { 1, 1 };
    enc(m, CU_TENSOR_MAP_DATA_TYPE_FLOAT16, 2, p, dims, strides, box, es,
        CU_TENSOR_MAP_INTERLEAVE_NONE, CU_TENSOR_MAP_SWIZZLE_128B,
        CU_TENSOR_MAP_L2_PROMOTION_L2_128B, CU_TENSOR_MAP_FLOAT_OOB_FILL_NONE);
}

extern "C" void kernel_launch(void* const* d_in, const int* in_sizes, int n_in,
                              void* d_out, int out_size)
{
    const float* act[3] = { (const float*)d_in[0], (const float*)d_in[1], (const float*)d_in[2] };
    const float* W[4]   = { (const float*)d_in[3], (const float*)d_in[5], (const float*)d_in[7], (const float*)d_in[9] };
    const float* bia[4] = { (const float*)d_in[4], (const float*)d_in[6], (const float*)d_in[8], (const float*)d_in[10] };
    float* out = (float*)d_out;

    __half *pact, *pwt, *pao, *pqkv;
    float* pbc;
    cudaGetSymbolAddress((void**)&pact, g_act);
    cudaGetSymbolAddress((void**)&pwt,  g_wt);
    cudaGetSymbolAddress((void**)&pao,  g_ao);
    cudaGetSymbolAddress((void**)&pqkv, g_qkvs);
    cudaGetSymbolAddress((void**)&pbc,  g_biasc);

    PFN_tmEncode enc = nullptr;
    cudaDriverEntryPointQueryResult qr;
    cudaGetDriverEntryPointByVersion("cuTensorMapEncodeTiled", (void**)&enc, 12000,
                                     cudaEnableDefault, &qr);

    const size_t WM = (size_t)DMODEL * DMODEL;

    static QkvMaps qkvmaps;
    static CUtensorMap mAao, mBo, mQKV[3];
    for (int i = 0; i < 3; i++) {
        make_map(enc, &qkvmaps.a[i], pact + (size_t)i * MTOT * DMODEL, MTOT, DMODEL, BK, 128);
        make_map(enc, &qkvmaps.b[i], pwt + (size_t)i * WM, DMODEL, DMODEL, BK, 128);
    }
    make_map(enc, &mAao, pao, MTOT, 2*DMODEL, BK, 128);
    make_map(enc, &mBo, pwt + 3*WM, DMODEL, DMODEL, BK, 128);
    for (int i = 0; i < 3; i++)
        make_map(enc, &mQKV[i], pqkv + i * QKVPART, (uint64_t)BHTOT * SEQ, DHEAD,
                 DHEAD, (i == 0) ? QT : KT);

    cudaFuncSetAttribute(gemm_qkv, cudaFuncAttributeMaxDynamicSharedMemorySize, GSMEM);
    cudaFuncSetAttribute(gemm_out, cudaFuncAttributeMaxDynamicSharedMemorySize, GSMEM);
    cudaFuncSetAttribute(attn_mma, cudaFuncAttributeMaxDynamicSharedMemorySize, ASMEM);

    // 1. fused preprocessing (ONE launch)
    pre_kernel<<<PRE_TOTAL, 256>>>(act[0], act[1], act[2],
                                   W[0], W[1], W[2], W[3],
                                   bia[0], bia[1], bia[2],
                                   pact, pwt, pbc);

    // 2. fused QKV projections (1-product, one launch) -> fp16 Q,K,V
    gemm_qkv<<<dim3(DMODEL/128, MTOT/128, 3), 256, GSMEM>>>(qkvmaps, pbc, pqkv);

    // 3. attention (fp16 HMMA, f16x2 softmax), writes split AO
    attn_mma<<<dim3(SEQ / QT, BHTOT), 256, ASMEM>>>(mQKV[0], mQKV[1], mQKV[2], pao);

    // 4. output projection (2-product on split AO)
    gemm_out<<<dim3(DMODEL/128, MTOT/128), 256, GSMEM>>>(mAao, mBo, bia[3], out);
}

// round 16
// speedup vs baseline: 1.0605x; 1.0041x over previous
#include <cuda_runtime.h>
#include <cuda.h>
#include <cuda_fp16.h>
#include <cstdint>

#define BATCH 2
#define SEQ   2048
#define DMODEL 1024
#define NHEAD 16
#define DHEAD 64
#define MTOT  (BATCH*SEQ)          // 4096
#define BHTOT (BATCH*NHEAD)        // 32
#define QKVPART ((size_t)BHTOT*SEQ*DHEAD)

// 0.125 * log2(e), folded into Wq/bq at preprocessing time.
#define QSCALE 0.1803368801111832f

// ---------------------------------------------------------------------------
// Device scratch
// ---------------------------------------------------------------------------
__device__ __half g_act[3u*MTOT*DMODEL];       // activations fp16 hi only
__device__ __half g_wt[4u*DMODEL*DMODEL];      // W^T fp16 hi only; segs q,k,v,o
__device__ __half g_ao[(size_t)MTOT*2*DMODEL]; // attention out split (hi|lo)
__device__ __half g_qkvs[3*QKVPART];           // Qh,Kh,Vh [BH][S][64]
__device__ float g_biasc[3*DMODEL];            // concat bq*QSCALE|bk|bv

// ---------------------------------------------------------------------------
// PTX helpers (legal at virtual arch compute_103)
// ---------------------------------------------------------------------------
__device__ __forceinline__ uint32_t smem_u32(const void* p) {
    uint32_t a;
    asm("{ .reg .u64 t; cvta.to.shared.u64 t, %1; cvt.u32.u64 %0, t; }" : "=r"(a) : "l"(p));
    return a;
}

// Programmatic dependent launch controls (no-ops when not launched with PDL)
#define GDC_LAUNCH() asm volatile("griddepcontrol.launch_dependents;" ::: "memory")
#define GDC_WAIT()   asm volatile("griddepcontrol.wait;" ::: "memory")

#define MBARRIER_INIT(addr, cnt) \
    asm volatile("mbarrier.init.shared.b64 [%0], %1;" :: "r"((uint32_t)(addr)), "r"((uint32_t)(cnt)) : "memory")
#define MBARRIER_EXPECT_TX(addr, bytes) \
    asm volatile("mbarrier.arrive.expect_tx.shared.b64 _, [%0], %1;" :: "r"((uint32_t)(addr)), "r"((uint32_t)(bytes)) : "memory")
#define MBARRIER_ARRIVE(addr) \
    asm volatile("mbarrier.arrive.release.cta.shared::cta.b64 _, [%0];" :: "r"((uint32_t)(addr)) : "memory")

#define MBARRIER_WAIT_PARITY(mbar_smem_addr, phase_parity) do { \
    uint32_t _mbar = (uint32_t)(mbar_smem_addr); \
    uint32_t _parity = (uint32_t)(phase_parity); \
    uint32_t _done; \
    asm volatile( \
        "{\n\t.reg .pred p;\n\t" \
        "mbarrier.try_wait.parity.acquire.cta.shared::cta.b64 p, [%1], %2;\n\t" \
        "selp.b32 %0, 1, 0, p;\n\t}" \
        : "=r"(_done) : "r"(_mbar), "r"(_parity) : "memory"); \
    if (!_done) { \
        asm volatile( \
            "{\n\t.reg .pred P1;\n\t" \
            "WAIT_LOOP_%=:\n\t" \
            "mbarrier.try_wait.parity.acquire.cta.shared::cta.b64 P1, [%0], %1, 0x989680;\n\t" \
            "@P1 bra.uni WAIT_DONE_%=;\n\t" \
            "bra.uni WAIT_LOOP_%=;\n\t" \
            "WAIT_DONE_%=:\n\t}" \
            :: "r"(_mbar), "r"(_parity) : "memory"); \
    } \
} while(0)

__device__ __forceinline__ void tma2d(uint32_t dst, const CUtensorMap* m, int x, int y, uint32_t bar) {
    asm volatile(
        "cp.async.bulk.tensor.2d.shared::cta.global.tile.mbarrier::complete_tx::bytes "
        "[%0], [%1, {%2, %3}], [%4];"
        :: "r"(dst), "l"(m), "r"(x), "r"(y), "r"(bar) : "memory");
}

__device__ __forceinline__ void ldsm_x4(uint32_t& r0, uint32_t& r1, uint32_t& r2, uint32_t& r3,
                                        uint32_t addr) {
    asm volatile("ldmatrix.sync.aligned.m8n8.x4.shared.b16 {%0,%1,%2,%3}, [%4];"
                 : "=r"(r0), "=r"(r1), "=r"(r2), "=r"(r3) : "r"(addr));
}
__device__ __forceinline__ void ldsm_x4_t(uint32_t& r0, uint32_t& r1, uint32_t& r2, uint32_t& r3,
                                          uint32_t addr) {
    asm volatile("ldmatrix.sync.aligned.m8n8.x4.trans.shared.b16 {%0,%1,%2,%3}, [%4];"
                 : "=r"(r0), "=r"(r1), "=r"(r2), "=r"(r3) : "r"(addr));
}

// fp16 mma, fp32 accum
__device__ __forceinline__ void mma16816h(float* c, const uint32_t* a, uint32_t b0, uint32_t b1) {
    asm volatile(
        "mma.sync.aligned.m16n8k16.row.col.f32.f16.f16.f32 "
        "{%0,%1,%2,%3}, {%4,%5,%6,%7}, {%8,%9}, {%0,%1,%2,%3};"
        : "+f"(c[0]), "+f"(c[1]), "+f"(c[2]), "+f"(c[3])
        : "r"(a[0]), "r"(a[1]), "r"(a[2]), "r"(a[3]), "r"(b0), "r"(b1));
}

__device__ __forceinline__ uint32_t pack2_f16(float x0, float x1) {
    uint32_t u;
    asm("cvt.rn.f16x2.f32 %0, %1, %2;" : "=r"(u) : "f"(x1), "f"(x0));
    return u;
}
__device__ __forceinline__ void split_pack2_f16(float x0, float x1, uint32_t& hp, uint32_t& lp) {
    hp = pack2_f16(x0, x1);
    __half2 hh = *reinterpret_cast<__half2*>(&hp);
    lp = pack2_f16(x0 - __low2float(hh), x1 - __high2float(hh));
}
__device__ __forceinline__ float ex2(float x) {
    float y; asm("ex2.approx.f32 %0, %1;" : "=f"(y) : "f"(x)); return y;
}
__device__ __forceinline__ uint32_t ex2_f16x2(uint32_t x) {
    uint32_t y; asm("ex2.approx.f16x2 %0, %1;" : "=r"(y) : "r"(x)); return y;
}

// smem address for 16B unit `u` of row `r` in a SW128 tile (128B rows)
__device__ __forceinline__ uint32_t ldsm_addr(uint32_t base, int r, int u) {
    return base + (uint32_t)r * 128u + (uint32_t)((u ^ (r & 7)) << 4);
}

// ---------------------------------------------------------------------------
// Fused preprocessing: ONE launch.
// ---------------------------------------------------------------------------
#define PRE_SPLIT_BLKS 12288
#define PRE_WT_BLKS    4096
#define PRE_BIAS_BLKS  12
#define PRE_TOTAL (PRE_SPLIT_BLKS + PRE_WT_BLKS + PRE_BIAS_BLKS)

__global__ void __launch_bounds__(256)
pre_kernel(const float* __restrict__ q, const float* __restrict__ k,
           const float* __restrict__ v,
           const float* __restrict__ Wq, const float* __restrict__ Wk,
           const float* __restrict__ Wv, const float* __restrict__ Wo,
           const float* __restrict__ bq, const float* __restrict__ bk,
           const float* __restrict__ bv,
           __half* __restrict__ actbase, __half* __restrict__ Tbase,
           float* __restrict__ biasc)
{
    __shared__ float t[32][33];
    const int blk = blockIdx.x;
    const int tid = threadIdx.x;

    if (blk < PRE_SPLIT_BLKS) {
        const int which = blk >> 12;
        const int m = blk & 4095;
        const float* x = (which == 0) ? q : (which == 1) ? k : v;
        __half* dst = actbase + (size_t)which * MTOT * DMODEL;
        const int k4 = tid * 4;
        float4 val = *(const float4*)&x[(size_t)m * DMODEL + k4];
        __half* hi = dst + (size_t)m * DMODEL + k4;
        *(uint32_t*)(hi)     = pack2_f16(val.x, val.y);
        *(uint32_t*)(hi + 2) = pack2_f16(val.z, val.w);
    } else if (blk < PRE_SPLIT_BLKS + PRE_WT_BLKS) {
        const int r = blk - PRE_SPLIT_BLKS;
        const int which = r >> 10;
        const int rem = r & 1023;
        const float* W = (which == 0) ? Wq : (which == 1) ? Wk
                       : (which == 2) ? Wv : Wo;
        const float sc = (which == 0) ? QSCALE : 1.0f;
        __half* T = Tbase + (size_t)which * DMODEL * DMODEL;
        const int n0 = (rem & 31) * 32;
        const int k0 = (rem >> 5) * 32;
        const int tx = tid & 31, ty = tid >> 5;
#pragma unroll
        for (int i = 0; i < 4; i++)
            t[ty + 8*i][tx] = W[(size_t)(k0 + ty + 8*i) * DMODEL + n0 + tx];
        __syncthreads();
#pragma unroll
        for (int i = 0; i < 4; i++) {
            const int n = n0 + ty + 8*i;
            const int kk = k0 + tx;
            T[(size_t)n * DMODEL + kk] = __float2half(t[tx][ty + 8*i] * sc);
        }
    } else {
        const int i = (blk - PRE_SPLIT_BLKS - PRE_WT_BLKS) * 256 + tid;
        const float* s = (i < 1024) ? bq : (i < 2048) ? bk : bv;
        const float sc = (i < 1024) ? QSCALE : 1.0f;
        biasc[i] = s[i & 1023] * sc;
    }
    GDC_LAUNCH();
}

// ---------------------------------------------------------------------------
// fp16 HMMA GEMM core, K=1024.
// NPROD=1: C = Ah*Bh (3-stage).  NPROD=2: C = Ah*Bh + Al*Bh (2-stage).
// GDC_WAIT before first dependent TMA; GDC_LAUNCH after mainloop.
// ---------------------------------------------------------------------------
#define BK       64
#define NCHUNK   16
#define GTILE    16384
#define GSMEM    (1024 + 6*GTILE)

template<int MODE, int NPROD>
__device__ __forceinline__ void gemm_core(
    const CUtensorMap* tmA, const CUtensorMap* tmB,
    const float* __restrict__ bias, float* __restrict__ C,
    __half* __restrict__ Ohi, int bm, int bn)
{
    constexpr int NSTG = (NPROD == 1) ? 3 : 2;
    constexpr int SSZ  = (NPROD == 1) ? 2*GTILE : 3*GTILE;

    extern __shared__ char sm_raw[];
    const uint32_t sb = smem_u32(sm_raw);
    const uint32_t tiles = (sb + 1024) & ~1023u;
    const int tid = threadIdx.x;
    const int lane = tid & 31, wid = tid >> 5;
    const int wm = wid & 3, wn = wid >> 2;

    const uint32_t FULL = sb;
    const uint32_t EMPTY = sb + 24;

    if (tid == 0) {
#pragma unroll
        for (int s = 0; s < NSTG; s++) {
            MBARRIER_INIT(FULL + 8*s, 1);
            MBARRIER_INIT(EMPTY + 8*s, 8);
        }
    }
    __syncthreads();

    GDC_WAIT();   // inputs produced by the previous kernel in the PDL chain

    if (tid == 0) {
#pragma unroll
        for (int s = 0; s < NSTG; s++) {
            MBARRIER_EXPECT_TX(FULL + 8*s, SSZ);
            const uint32_t st = tiles + s*SSZ;
            if (NPROD == 1) {
                tma2d(st,         tmA, s*BK, bm, FULL + 8*s);
                tma2d(st + GTILE, tmB, s*BK, bn, FULL + 8*s);
            } else {
                tma2d(st,           tmA, s*BK,          bm, FULL + 8*s);
                tma2d(st + GTILE,   tmA, DMODEL + s*BK, bm, FULL + 8*s);
                tma2d(st + 2*GTILE, tmB, s*BK,          bn, FULL + 8*s);
            }
        }
    }

    float acc[2][8][4];
#pragma unroll
    for (int i = 0; i < 2; i++)
#pragma unroll
        for (int j = 0; j < 8; j++)
#pragma unroll
            for (int q = 0; q < 4; q++) acc[i][j][q] = 0.f;

    const int lrow = lane & 15;
    const int lcolhalf = lane >> 4;
    const int sw = lane & 7;

    for (int c = 0; c < NCHUNK; c++) {
        const int s = c % NSTG;
        const int ph = (c / NSTG) & 1;
        MBARRIER_WAIT_PARITY(FULL + 8*s, ph);

        const uint32_t Ah = tiles + s*SSZ;
        const uint32_t Al = Ah + GTILE;
        const uint32_t Bs = Ah + (NPROD == 1 ? GTILE : 2*GTILE);

#pragma unroll
        for (int kk = 0; kk < 4; kk++) {
            const int cidx = 2*kk + lcolhalf;
            const uint32_t coff = (uint32_t)((cidx ^ sw) << 4);

            uint32_t ah[2][4], al[2][4];
#pragma unroll
            for (int mi = 0; mi < 2; mi++) {
                const int r = wm*32 + mi*16 + lrow;
                ldsm_x4(ah[mi][0], ah[mi][1], ah[mi][2], ah[mi][3],
                        Ah + (uint32_t)r*128 + coff);
                if (NPROD == 2)
                    ldsm_x4(al[mi][0], al[mi][1], al[mi][2], al[mi][3],
                            Al + (uint32_t)r*128 + coff);
            }
            uint32_t b[4][4];
#pragma unroll
            for (int ni = 0; ni < 4; ni++) {
                const int r = wn*64 + ni*16 + lrow;
                ldsm_x4(b[ni][0], b[ni][1], b[ni][2], b[ni][3],
                        Bs + (uint32_t)r*128 + coff);
            }
#pragma unroll
            for (int mi = 0; mi < 2; mi++)
#pragma unroll
                for (int ni = 0; ni < 4; ni++) {
                    mma16816h(acc[mi][2*ni+0], ah[mi], b[ni][0], b[ni][2]);
                    mma16816h(acc[mi][2*ni+1], ah[mi], b[ni][1], b[ni][3]);
                    if (NPROD == 2) {
                        mma16816h(acc[mi][2*ni+0], al[mi], b[ni][0], b[ni][2]);
                        mma16816h(acc[mi][2*ni+1], al[mi], b[ni][1], b[ni][3]);
                    }
                }
        }
        if (lane == 0) MBARRIER_ARRIVE(EMPTY + 8*s);
        if (tid == 0 && c + NSTG < NCHUNK) {
            MBARRIER_WAIT_PARITY(EMPTY + 8*s, ph);
            MBARRIER_EXPECT_TX(FULL + 8*s, SSZ);
            const int kx = (c + NSTG) * BK;
            if (NPROD == 1) {
                tma2d(Ah, tmA, kx, bm, FULL + 8*s);
                tma2d(Bs, tmB, kx, bn, FULL + 8*s);
            } else {
                tma2d(Ah, tmA, kx,          bm, FULL + 8*s);
                tma2d(Al, tmA, DMODEL + kx, bm, FULL + 8*s);
                tma2d(Bs, tmB, kx,          bn, FULL + 8*s);
            }
        }
    }

    GDC_LAUNCH();   // let the dependent grid start launching during our epilogue

    const int grp = lane >> 2;
    const int qd  = lane & 3;
#pragma unroll
    for (int mi = 0; mi < 2; mi++) {
#pragma unroll
        for (int nj = 0; nj < 8; nj++) {
            const int col = bn + wn*64 + nj*8 + qd*2;
            const float b0 = __ldg(&bias[col]);
            const float b1 = __ldg(&bias[col + 1]);
#pragma unroll
            for (int half = 0; half < 2; half++) {
                const int m = bm + wm*32 + mi*16 + grp + half*8;
                const float v0 = acc[mi][nj][2*half+0] + b0;
                const float v1 = acc[mi][nj][2*half+1] + b1;
                if (MODE == 0) {
                    *(float2*)&C[(size_t)m * DMODEL + col] = make_float2(v0, v1);
                } else {
                    const int b = m >> 11, srow = m & 2047;
                    const int h = col >> 6, d = col & 63;
                    const size_t off = (((size_t)b * NHEAD + h) * SEQ + srow) * DHEAD + d;
                    *(uint32_t*)&Ohi[off] = pack2_f16(v0, v1);
                }
            }
        }
    }
}

struct QkvMaps { CUtensorMap a[3]; CUtensorMap b[3]; };

__global__ void __launch_bounds__(256, 2)
gemm_qkv(const __grid_constant__ QkvMaps maps,
         const float* __restrict__ biasc, __half* __restrict__ qkvbase)
{
    const int i = blockIdx.z;
    gemm_core<1, 1>(&maps.a[i], &maps.b[i], biasc + i * DMODEL, nullptr,
                    qkvbase + (size_t)i * QKVPART,
                    blockIdx.y * 128, blockIdx.x * 128);
}

__global__ void __launch_bounds__(256, 2)
gemm_out(const __grid_constant__ CUtensorMap tmA,
         const __grid_constant__ CUtensorMap tmB,
         const float* __restrict__ bias, float* __restrict__ C)
{
    gemm_core<0, 2>(&tmA, &tmB, bias, C, nullptr, blockIdx.y * 128, blockIdx.x * 128);
}

// ---------------------------------------------------------------------------
// Flash attention, pure fp16 HMMA, f16x2 exp2 softmax. PDL chained.
// ---------------------------------------------------------------------------
#define QT 128
#define KT 64
#define AT_TILEQ  16384
#define AT_TILEKV 8192
#define AT_STAGE  (2*AT_TILEKV)      // Kh, Vh
#define ASMEM (1024 + AT_TILEQ + 2*AT_STAGE)

__global__ void __launch_bounds__(256, 2)
attn_mma(const __grid_constant__ CUtensorMap tmQ,
         const __grid_constant__ CUtensorMap tmK,
         const __grid_constant__ CUtensorMap tmV,
         __half* __restrict__ AO)
{
    extern __shared__ char smraw[];
    const uint32_t sb = smem_u32(smraw);
    const uint32_t tiles = (sb + 1024) & ~1023u;
    const uint32_t Qs = tiles;
    const uint32_t STG = tiles + AT_TILEQ;
    const int tid = threadIdx.x, lane = tid & 31, wid = tid >> 5;
    const int bh = blockIdx.y;
    const int q0 = blockIdx.x * QT;
    const int gy = bh * SEQ;

    const uint32_t BQ = sb, BF = sb + 8, BE = sb + 24;
    if (tid == 0) {
        MBARRIER_INIT(BQ, 1);
        MBARRIER_INIT(BF + 0, 1);
        MBARRIER_INIT(BF + 8, 1);
        MBARRIER_INIT(BE + 0, 8);
        MBARRIER_INIT(BE + 8, 8);
    }
    __syncthreads();

    GDC_WAIT();   // Q/K/V produced by gemm_qkv

    if (tid == 0) {
        MBARRIER_EXPECT_TX(BQ, AT_TILEQ);
        tma2d(Qs, &tmQ, 0, gy + q0, BQ);
#pragma unroll
        for (int s = 0; s < 2; s++) {
            const uint32_t st = STG + s*AT_STAGE;
            MBARRIER_EXPECT_TX(BF + 8*s, AT_STAGE);
            tma2d(st,              &tmK, 0, gy + s*KT, BF + 8*s);
            tma2d(st + AT_TILEKV,  &tmV, 0, gy + s*KT, BF + 8*s);
        }
    }

    float m_run[2] = { -1e30f, -1e30f };
    float l_run[2] = { 0.f, 0.f };
    float o_acc[8][4];
#pragma unroll
    for (int i = 0; i < 8; i++)
#pragma unroll
        for (int j = 0; j < 4; j++) o_acc[i][j] = 0.f;

    MBARRIER_WAIT_PARITY(BQ, 0);

    const int r0q = wid * 16;
    const int la7 = lane & 7;
    const int g01 = (lane >> 3) & 1;
    const int g23 = lane >> 4;

    uint32_t qf[4][4];
#pragma unroll
    for (int j = 0; j < 4; j++) {
        const int rr = r0q + la7 + g01*8;
        const int uu = 2*j + g23;
        ldsm_x4(qf[j][0], qf[j][1], qf[j][2], qf[j][3], ldsm_addr(Qs, rr, uu));
    }

    for (int kt = 0; kt < SEQ / KT; kt++) {
        const int s = kt & 1, ph = (kt >> 1) & 1;
        MBARRIER_WAIT_PARITY(BF + 8*s, ph);
        const uint32_t Kh = STG + s*AT_STAGE;
        const uint32_t Vh = Kh + AT_TILEKV;

        float sf[8][4];
#pragma unroll
        for (int i = 0; i < 8; i++)
#pragma unroll
            for (int j = 0; j < 4; j++) sf[i][j] = 0.f;

#pragma unroll
        for (int j = 0; j < 4; j++) {
#pragma unroll
            for (int np = 0; np < 4; np++) {
                const int rr = np*16 + la7 + g23*8;
                const int uu = 2*j + g01;
                uint32_t k0,k1,k2,k3;
                ldsm_x4(k0,k1,k2,k3, ldsm_addr(Kh, rr, uu));
                mma16816h(sf[2*np+0], qf[j], k0, k1);
                mma16816h(sf[2*np+1], qf[j], k2, k3);
            }
        }

        // ---- online softmax: exp2 in fp16x2 pairs (P fragments) ----
        uint32_t psf[8][2];
#pragma unroll
        for (int hf = 0; hf < 2; hf++) {
            float mx = -1e30f;
#pragma unroll
            for (int nt = 0; nt < 8; nt++)
                mx = fmaxf(mx, fmaxf(sf[nt][2*hf], sf[nt][2*hf+1]));
            mx = fmaxf(mx, __shfl_xor_sync(0xffffffffu, mx, 1));
            mx = fmaxf(mx, __shfl_xor_sync(0xffffffffu, mx, 2));
            const float mnew = fmaxf(m_run[hf], mx);
            const float corr = ex2(m_run[hf] - mnew);
            float sum = 0.f;
#pragma unroll
            for (int nt = 0; nt < 8; nt++) {
                const uint32_t u = pack2_f16(sf[nt][2*hf] - mnew,
                                             sf[nt][2*hf+1] - mnew);
                const uint32_t p2 = ex2_f16x2(u);
                psf[nt][hf] = p2;
                const float2 pf = __half22float2(*reinterpret_cast<const __half2*>(&p2));
                sum += pf.x + pf.y;
            }
            sum += __shfl_xor_sync(0xffffffffu, sum, 1);
            sum += __shfl_xor_sync(0xffffffffu, sum, 2);
            l_run[hf] = l_run[hf] * corr + sum;
            m_run[hf] = mnew;
#pragma unroll
            for (int nt = 0; nt < 8; nt++) {
                o_acc[nt][2*hf]   *= corr;
                o_acc[nt][2*hf+1] *= corr;
            }
        }

        // ---- O += P V ----
#pragma unroll
        for (int j = 0; j < 4; j++) {
            uint32_t ph16[4];
#pragma unroll
            for (int t = 0; t < 4; t++)
                ph16[t] = psf[2*j + (t >> 1)][t & 1];
#pragma unroll
            for (int np = 0; np < 4; np++) {
                const int rr = 16*j + la7 + g01*8;
                const int uu = 2*np + g23;
                uint32_t v0,v1,v2,v3;
                ldsm_x4_t(v0,v1,v2,v3, ldsm_addr(Vh, rr, uu));
                mma16816h(o_acc[2*np+0], ph16, v0, v1);
                mma16816h(o_acc[2*np+1], ph16, v2, v3);
            }
        }

        if (lane == 0) MBARRIER_ARRIVE(BE + 8*s);
        if (tid == 0 && kt + 2 < SEQ / KT) {
            MBARRIER_WAIT_PARITY(BE + 8*s, ph);
            const uint32_t st = STG + s*AT_STAGE;
            MBARRIER_EXPECT_TX(BF + 8*s, AT_STAGE);
            tma2d(st,             &tmK, 0, gy + (kt+2)*KT, BF + 8*s);
            tma2d(st + AT_TILEKV, &tmV, 0, gy + (kt+2)*KT, BF + 8*s);
        }
    }

    GDC_LAUNCH();   // gemm_out may start launching during our epilogue

    const int b = bh >> 4, h = bh & 15;
#pragma unroll
    for (int hf = 0; hf < 2; hf++) {
        const float inv = 1.f / l_run[hf];
        const int srow = q0 + r0q + (lane >> 2) + hf*8;
#pragma unroll
        for (int nt = 0; nt < 8; nt++) {
            const int d = nt*8 + (lane & 3)*2;
            const float f0 = o_acc[nt][2*hf]   * inv;
            const float f1 = o_acc[nt][2*hf+1] * inv;
            uint32_t hp, lp;
            split_pack2_f16(f0, f1, hp, lp);
            const size_t base = ((size_t)b * SEQ + srow) * 2 * DMODEL + h * DHEAD + d;
            *(uint32_t*)&AO[base]          = hp;
            *(uint32_t*)&AO[base + DMODEL] = lp;
        }
    }
}

// ---------------------------------------------------------------------------
// Host
// ---------------------------------------------------------------------------
typedef CUresult (*PFN_tmEncode)(CUtensorMap*, CUtensorMapDataType, cuuint32_t, void*,
                                 const cuuint64_t*, const cuuint64_t*, const cuuint32_t*,
                                 const cuuint32_t*, CUtensorMapInterleave, CUtensorMapSwizzle,
                                 CUtensorMapL2promotion, CUtensorMapFloatOOBfill);

static void make_map(PFN_tmEncode enc, CUtensorMap* m, void* p, uint64_t rows,
                     uint64_t width, uint32_t b0, uint32_t b1)
{
    cuuint64_t dims[2]    = { width, rows };
    cuuint64_t strides[1] = { width * 2 };
    cuuint32_t box[2]     = { b0, b1 };
    cuuint32_t es[2]      = { 1, 1 };
    enc(m, CU_TENSOR_MAP_DATA_TYPE_FLOAT16, 2, p, dims, strides, box, es,
        CU_TENSOR_MAP_INTERLEAVE_NONE, CU_TENSOR_MAP_SWIZZLE_128B,
        CU_TENSOR_MAP_L2_PROMOTION_L2_128B, CU_TENSOR_MAP_FLOAT_OOB_FILL_NONE);
}

extern "C" void kernel_launch(void* const* d_in, const int* in_sizes, int n_in,
                              void* d_out, int out_size)
{
    const float* act[3] = { (const float*)d_in[0], (const float*)d_in[1], (const float*)d_in[2] };
    const float* W[4]   = { (const float*)d_in[3], (const float*)d_in[5], (const float*)d_in[7], (const float*)d_in[9] };
    const float* bia[4] = { (const float*)d_in[4], (const float*)d_in[6], (const float*)d_in[8], (const float*)d_in[10] };
    float* out = (float*)d_out;

    __half *pact, *pwt, *pao, *pqkv;
    float* pbc;
    cudaGetSymbolAddress((void**)&pact, g_act);
    cudaGetSymbolAddress((void**)&pwt,  g_wt);
    cudaGetSymbolAddress((void**)&pao,  g_ao);
    cudaGetSymbolAddress((void**)&pqkv, g_qkvs);
    cudaGetSymbolAddress((void**)&pbc,  g_biasc);

    PFN_tmEncode enc = nullptr;
    cudaDriverEntryPointQueryResult qr;
    cudaGetDriverEntryPointByVersion("cuTensorMapEncodeTiled", (void**)&enc, 12000,
                                     cudaEnableDefault, &qr);

    const size_t WM = (size_t)DMODEL * DMODEL;

    static QkvMaps qkvmaps;
    static CUtensorMap mAao, mBo, mQKV[3];
    for (int i = 0; i < 3; i++) {
        make_map(enc, &qkvmaps.a[i], pact + (size_t)i * MTOT * DMODEL, MTOT, DMODEL, BK, 128);
        make_map(enc, &qkvmaps.b[i], pwt + (size_t)i * WM, DMODEL, DMODEL, BK, 128);
    }
    make_map(enc, &mAao, pao, MTOT, 2*DMODEL, BK, 128);
    make_map(enc, &mBo, pwt + 3*WM, DMODEL, DMODEL, BK, 128);
    for (int i = 0; i < 3; i++)
        make_map(enc, &mQKV[i], pqkv + i * QKVPART, (uint64_t)BHTOT * SEQ, DHEAD,
                 DHEAD, (i == 0) ? QT : KT);

    cudaFuncSetAttribute(gemm_qkv, cudaFuncAttributeMaxDynamicSharedMemorySize, GSMEM);
    cudaFuncSetAttribute(gemm_out, cudaFuncAttributeMaxDynamicSharedMemorySize, GSMEM);
    cudaFuncSetAttribute(attn_mma, cudaFuncAttributeMaxDynamicSharedMemorySize, ASMEM);

    // PDL attribute for dependent launches
    cudaLaunchAttribute pdl;
    pdl.id = cudaLaunchAttributeProgrammaticStreamSerialization;
    pdl.val.programmaticStreamSerializationAllowed = 1;

    // 1. fused preprocessing (primary)
    pre_kernel<<<PRE_TOTAL, 256>>>(act[0], act[1], act[2],
                                   W[0], W[1], W[2], W[3],
                                   bia[0], bia[1], bia[2],
                                   pact, pwt, pbc);

    // 2. fused QKV projections (PDL-dependent on pre)
    {
        cudaLaunchConfig_t cfg = {};
        cfg.gridDim = dim3(DMODEL/128, MTOT/128, 3);
        cfg.blockDim = dim3(256, 1, 1);
        cfg.dynamicSmemBytes = GSMEM;
        cfg.stream = 0;
        cfg.attrs = &pdl;
        cfg.numAttrs = 1;
        cudaLaunchKernelEx(&cfg, gemm_qkv, qkvmaps, (const float*)pbc, pqkv);
    }

    // 3. attention (PDL-dependent on qkv)
    {
        cudaLaunchConfig_t cfg = {};
        cfg.gridDim = dim3(SEQ / QT, BHTOT, 1);
        cfg.blockDim = dim3(256, 1, 1);
        cfg.dynamicSmemBytes = ASMEM;
        cfg.stream = 0;
        cfg.attrs = &pdl;
        cfg.numAttrs = 1;
        cudaLaunchKernelEx(&cfg, attn_mma, mQKV[0], mQKV[1], mQKV[2], pao);
    }

    // 4. output projection (PDL-dependent on attention)
    {
        cudaLaunchConfig_t cfg = {};
        cfg.gridDim = dim3(DMODEL/128, MTOT/128, 1);
        cfg.blockDim = dim3(256, 1, 1);
        cfg.dynamicSmemBytes = GSMEM;
        cfg.stream = 0;
        cfg.attrs = &pdl;
        cfg.numAttrs = 1;
        cudaLaunchKernelEx(&cfg, gemm_out, mAao, mBo, (const float*)bia[3], out);
    }
}

// round 17
// speedup vs baseline: 1.0638x; 1.0031x over previous
#include <cuda_runtime.h>
#include <cuda.h>
#include <cuda_fp16.h>
#include <cstdint>

#define BATCH 2
#define SEQ   2048
#define DMODEL 1024
#define NHEAD 16
#define DHEAD 64
#define MTOT  (BATCH*SEQ)          // 4096
#define BHTOT (BATCH*NHEAD)        // 32
#define QKVPART ((size_t)BHTOT*SEQ*DHEAD)

// 0.125 * log2(e), folded into Wq/bq at preprocessing time.
#define QSCALE 0.1803368801111832f

// ---------------------------------------------------------------------------
// Device scratch
// ---------------------------------------------------------------------------
__device__ __half g_act[3u*MTOT*DMODEL];       // activations fp16 hi only
__device__ __half g_wt[4u*DMODEL*DMODEL];      // W^T fp16 hi only; segs q,k,v,o
__device__ __half g_ao[(size_t)MTOT*2*DMODEL]; // attention out split (hi|lo)
__device__ __half g_qkvs[3*QKVPART];           // Qh,Kh,Vh [BH][S][64]
__device__ float g_biasc[3*DMODEL];            // concat bq*QSCALE|bk|bv
__device__ unsigned g_cnt[MTOT/128];           // per-128-row AO readiness (16 heads each)

// ---------------------------------------------------------------------------
// PTX helpers (legal at virtual arch compute_103)
// ---------------------------------------------------------------------------
__device__ __forceinline__ uint32_t smem_u32(const void* p) {
    uint32_t a;
    asm("{ .reg .u64 t; cvta.to.shared.u64 t, %1; cvt.u32.u64 %0, t; }" : "=r"(a) : "l"(p));
    return a;
}

// Programmatic dependent launch controls
#define GDC_LAUNCH() asm volatile("griddepcontrol.launch_dependents;" ::: "memory")
#define GDC_WAIT()   asm volatile("griddepcontrol.wait;" ::: "memory")

__device__ __forceinline__ uint32_t ld_acq_u32(const unsigned* p) {
    uint32_t v;
    asm volatile("ld.acquire.gpu.global.u32 %0, [%1];" : "=r"(v) : "l"(p) : "memory");
    return v;
}
__device__ __forceinline__ void red_rel_add(unsigned* p, uint32_t v) {
    asm volatile("red.release.gpu.global.add.u32 [%0], %1;" :: "l"(p), "r"(v) : "memory");
}

#define MBARRIER_INIT(addr, cnt) \
    asm volatile("mbarrier.init.shared.b64 [%0], %1;" :: "r"((uint32_t)(addr)), "r"((uint32_t)(cnt)) : "memory")
#define MBARRIER_EXPECT_TX(addr, bytes) \
    asm volatile("mbarrier.arrive.expect_tx.shared.b64 _, [%0], %1;" :: "r"((uint32_t)(addr)), "r"((uint32_t)(bytes)) : "memory")
#define MBARRIER_ARRIVE(addr) \
    asm volatile("mbarrier.arrive.release.cta.shared::cta.b64 _, [%0];" :: "r"((uint32_t)(addr)) : "memory")

#define MBARRIER_WAIT_PARITY(mbar_smem_addr, phase_parity) do { \
    uint32_t _mbar = (uint32_t)(mbar_smem_addr); \
    uint32_t _parity = (uint32_t)(phase_parity); \
    uint32_t _done; \
    asm volatile( \
        "{\n\t.reg .pred p;\n\t" \
        "mbarrier.try_wait.parity.acquire.cta.shared::cta.b64 p, [%1], %2;\n\t" \
        "selp.b32 %0, 1, 0, p;\n\t}" \
        : "=r"(_done) : "r"(_mbar), "r"(_parity) : "memory"); \
    if (!_done) { \
        asm volatile( \
            "{\n\t.reg .pred P1;\n\t" \
            "WAIT_LOOP_%=:\n\t" \
            "mbarrier.try_wait.parity.acquire.cta.shared::cta.b64 P1, [%0], %1, 0x989680;\n\t" \
            "@P1 bra.uni WAIT_DONE_%=;\n\t" \
            "bra.uni WAIT_LOOP_%=;\n\t" \
            "WAIT_DONE_%=:\n\t}" \
            :: "r"(_mbar), "r"(_parity) : "memory"); \
    } \
} while(0)

__device__ __forceinline__ void tma2d(uint32_t dst, const CUtensorMap* m, int x, int y, uint32_t bar) {
    asm volatile(
        "cp.async.bulk.tensor.2d.shared::cta.global.tile.mbarrier::complete_tx::bytes "
        "[%0], [%1, {%2, %3}], [%4];"
        :: "r"(dst), "l"(m), "r"(x), "r"(y), "r"(bar) : "memory");
}

__device__ __forceinline__ void ldsm_x4(uint32_t& r0, uint32_t& r1, uint32_t& r2, uint32_t& r3,
                                        uint32_t addr) {
    asm volatile("ldmatrix.sync.aligned.m8n8.x4.shared.b16 {%0,%1,%2,%3}, [%4];"
                 : "=r"(r0), "=r"(r1), "=r"(r2), "=r"(r3) : "r"(addr));
}
__device__ __forceinline__ void ldsm_x4_t(uint32_t& r0, uint32_t& r1, uint32_t& r2, uint32_t& r3,
                                          uint32_t addr) {
    asm volatile("ldmatrix.sync.aligned.m8n8.x4.trans.shared.b16 {%0,%1,%2,%3}, [%4];"
                 : "=r"(r0), "=r"(r1), "=r"(r2), "=r"(r3) : "r"(addr));
}

// fp16 mma, fp32 accum
__device__ __forceinline__ void mma16816h(float* c, const uint32_t* a, uint32_t b0, uint32_t b1) {
    asm volatile(
        "mma.sync.aligned.m16n8k16.row.col.f32.f16.f16.f32 "
        "{%0,%1,%2,%3}, {%4,%5,%6,%7}, {%8,%9}, {%0,%1,%2,%3};"
        : "+f"(c[0]), "+f"(c[1]), "+f"(c[2]), "+f"(c[3])
        : "r"(a[0]), "r"(a[1]), "r"(a[2]), "r"(a[3]), "r"(b0), "r"(b1));
}

__device__ __forceinline__ uint32_t pack2_f16(float x0, float x1) {
    uint32_t u;
    asm("cvt.rn.f16x2.f32 %0, %1, %2;" : "=r"(u) : "f"(x1), "f"(x0));
    return u;
}
__device__ __forceinline__ void split_pack2_f16(float x0, float x1, uint32_t& hp, uint32_t& lp) {
    hp = pack2_f16(x0, x1);
    __half2 hh = *reinterpret_cast<__half2*>(&hp);
    lp = pack2_f16(x0 - __low2float(hh), x1 - __high2float(hh));
}
__device__ __forceinline__ float ex2(float x) {
    float y; asm("ex2.approx.f32 %0, %1;" : "=f"(y) : "f"(x)); return y;
}
__device__ __forceinline__ uint32_t ex2_f16x2(uint32_t x) {
    uint32_t y; asm("ex2.approx.f16x2 %0, %1;" : "=r"(y) : "r"(x)); return y;
}

// smem address for 16B unit `u` of row `r` in a SW128 tile (128B rows)
__device__ __forceinline__ uint32_t ldsm_addr(uint32_t base, int r, int u) {
    return base + (uint32_t)r * 128u + (uint32_t)((u ^ (r & 7)) << 4);
}

// ---------------------------------------------------------------------------
// Fused preprocessing: ONE launch.
// ---------------------------------------------------------------------------
#define PRE_SPLIT_BLKS 12288
#define PRE_WT_BLKS    4096
#define PRE_BIAS_BLKS  12
#define PRE_TOTAL (PRE_SPLIT_BLKS + PRE_WT_BLKS + PRE_BIAS_BLKS)

__global__ void __launch_bounds__(256)
pre_kernel(const float* __restrict__ q, const float* __restrict__ k,
           const float* __restrict__ v,
           const float* __restrict__ Wq, const float* __restrict__ Wk,
           const float* __restrict__ Wv, const float* __restrict__ Wo,
           const float* __restrict__ bq, const float* __restrict__ bk,
           const float* __restrict__ bv,
           __half* __restrict__ actbase, __half* __restrict__ Tbase,
           float* __restrict__ biasc)
{
    __shared__ float t[32][33];
    const int blk = blockIdx.x;
    const int tid = threadIdx.x;

    if (blk < PRE_SPLIT_BLKS) {
        const int which = blk >> 12;
        const int m = blk & 4095;
        const float* x = (which == 0) ? q : (which == 1) ? k : v;
        __half* dst = actbase + (size_t)which * MTOT * DMODEL;
        const int k4 = tid * 4;
        float4 val = *(const float4*)&x[(size_t)m * DMODEL + k4];
        __half* hi = dst + (size_t)m * DMODEL + k4;
        *(uint32_t*)(hi)     = pack2_f16(val.x, val.y);
        *(uint32_t*)(hi + 2) = pack2_f16(val.z, val.w);
    } else if (blk < PRE_SPLIT_BLKS + PRE_WT_BLKS) {
        const int r = blk - PRE_SPLIT_BLKS;
        const int which = r >> 10;
        const int rem = r & 1023;
        const float* W = (which == 0) ? Wq : (which == 1) ? Wk
                       : (which == 2) ? Wv : Wo;
        const float sc = (which == 0) ? QSCALE : 1.0f;
        __half* T = Tbase + (size_t)which * DMODEL * DMODEL;
        const int n0 = (rem & 31) * 32;
        const int k0 = (rem >> 5) * 32;
        const int tx = tid & 31, ty = tid >> 5;
#pragma unroll
        for (int i = 0; i < 4; i++)
            t[ty + 8*i][tx] = W[(size_t)(k0 + ty + 8*i) * DMODEL + n0 + tx];
        __syncthreads();
#pragma unroll
        for (int i = 0; i < 4; i++) {
            const int n = n0 + ty + 8*i;
            const int kk = k0 + tx;
            T[(size_t)n * DMODEL + kk] = __float2half(t[tx][ty + 8*i] * sc);
        }
    } else {
        const int i = (blk - PRE_SPLIT_BLKS - PRE_WT_BLKS) * 256 + tid;
        const float* s = (i < 1024) ? bq : (i < 2048) ? bk : bv;
        const float sc = (i < 1024) ? QSCALE : 1.0f;
        biasc[i] = s[i & 1023] * sc;
    }
    GDC_LAUNCH();
}

// ---------------------------------------------------------------------------
// fp16 HMMA GEMM core, K=1024.
// NPROD=1 (qkv): GDC_WAIT gate; zeroes g_cnt from CTA (0,0,0).
// NPROD=2 (out): fine-grained counter gate (16 attention producers per tile).
// ---------------------------------------------------------------------------
#define BK       64
#define NCHUNK   16
#define GTILE    16384
#define GSMEM    (1024 + 6*GTILE)

template<int MODE, int NPROD>
__device__ __forceinline__ void gemm_core(
    const CUtensorMap* tmA, const CUtensorMap* tmB,
    const float* __restrict__ bias, float* __restrict__ C,
    __half* __restrict__ Ohi, unsigned* cnt, int mb, int bm, int bn)
{
    constexpr int NSTG = (NPROD == 1) ? 3 : 2;
    constexpr int SSZ  = (NPROD == 1) ? 2*GTILE : 3*GTILE;

    extern __shared__ char sm_raw[];
    const uint32_t sb = smem_u32(sm_raw);
    const uint32_t tiles = (sb + 1024) & ~1023u;
    const int tid = threadIdx.x;
    const int lane = tid & 31, wid = tid >> 5;
    const int wm = wid & 3, wn = wid >> 2;

    const uint32_t FULL = sb;
    const uint32_t EMPTY = sb + 24;

    if (tid == 0) {
#pragma unroll
        for (int s = 0; s < NSTG; s++) {
            MBARRIER_INIT(FULL + 8*s, 1);
            MBARRIER_INIT(EMPTY + 8*s, 8);
        }
    }
    __syncthreads();

    if (NPROD == 1) {
        GDC_WAIT();   // inputs produced by pre_kernel
        // zero the AO readiness counters (once, before attention can run)
        if (blockIdx.x == 0 && blockIdx.y == 0 && blockIdx.z == 0 && tid < MTOT/128)
            cnt[tid] = 0;
        GDC_LAUNCH(); // early: attention enforces its dependency via GDC_WAIT
    }

    if (tid == 0) {
        if (NPROD == 2) {
            // wait for the 16 attention CTAs producing AO rows [bm, bm+128)
            while (ld_acq_u32(&cnt[mb]) < 16u) __nanosleep(128);
        }
#pragma unroll
        for (int s = 0; s < NSTG; s++) {
            MBARRIER_EXPECT_TX(FULL + 8*s, SSZ);
            const uint32_t st = tiles + s*SSZ;
            if (NPROD == 1) {
                tma2d(st,         tmA, s*BK, bm, FULL + 8*s);
                tma2d(st + GTILE, tmB, s*BK, bn, FULL + 8*s);
            } else {
                tma2d(st,           tmA, s*BK,          bm, FULL + 8*s);
                tma2d(st + GTILE,   tmA, DMODEL + s*BK, bm, FULL + 8*s);
                tma2d(st + 2*GTILE, tmB, s*BK,          bn, FULL + 8*s);
            }
        }
    }

    float acc[2][8][4];
#pragma unroll
    for (int i = 0; i < 2; i++)
#pragma unroll
        for (int j = 0; j < 8; j++)
#pragma unroll
            for (int q = 0; q < 4; q++) acc[i][j][q] = 0.f;

    const int lrow = lane & 15;
    const int lcolhalf = lane >> 4;
    const int sw = lane & 7;

    for (int c = 0; c < NCHUNK; c++) {
        const int s = c % NSTG;
        const int ph = (c / NSTG) & 1;
        MBARRIER_WAIT_PARITY(FULL + 8*s, ph);

        const uint32_t Ah = tiles + s*SSZ;
        const uint32_t Al = Ah + GTILE;
        const uint32_t Bs = Ah + (NPROD == 1 ? GTILE : 2*GTILE);

#pragma unroll
        for (int kk = 0; kk < 4; kk++) {
            const int cidx = 2*kk + lcolhalf;
            const uint32_t coff = (uint32_t)((cidx ^ sw) << 4);

            uint32_t ah[2][4], al[2][4];
#pragma unroll
            for (int mi = 0; mi < 2; mi++) {
                const int r = wm*32 + mi*16 + lrow;
                ldsm_x4(ah[mi][0], ah[mi][1], ah[mi][2], ah[mi][3],
                        Ah + (uint32_t)r*128 + coff);
                if (NPROD == 2)
                    ldsm_x4(al[mi][0], al[mi][1], al[mi][2], al[mi][3],
                            Al + (uint32_t)r*128 + coff);
            }
            uint32_t b[4][4];
#pragma unroll
            for (int ni = 0; ni < 4; ni++) {
                const int r = wn*64 + ni*16 + lrow;
                ldsm_x4(b[ni][0], b[ni][1], b[ni][2], b[ni][3],
                        Bs + (uint32_t)r*128 + coff);
            }
#pragma unroll
            for (int mi = 0; mi < 2; mi++)
#pragma unroll
                for (int ni = 0; ni < 4; ni++) {
                    mma16816h(acc[mi][2*ni+0], ah[mi], b[ni][0], b[ni][2]);
                    mma16816h(acc[mi][2*ni+1], ah[mi], b[ni][1], b[ni][3]);
                    if (NPROD == 2) {
                        mma16816h(acc[mi][2*ni+0], al[mi], b[ni][0], b[ni][2]);
                        mma16816h(acc[mi][2*ni+1], al[mi], b[ni][1], b[ni][3]);
                    }
                }
        }
        if (lane == 0) MBARRIER_ARRIVE(EMPTY + 8*s);
        if (tid == 0 && c + NSTG < NCHUNK) {
            MBARRIER_WAIT_PARITY(EMPTY + 8*s, ph);
            MBARRIER_EXPECT_TX(FULL + 8*s, SSZ);
            const int kx = (c + NSTG) * BK;
            if (NPROD == 1) {
                tma2d(Ah, tmA, kx, bm, FULL + 8*s);
                tma2d(Bs, tmB, kx, bn, FULL + 8*s);
            } else {
                tma2d(Ah, tmA, kx,          bm, FULL + 8*s);
                tma2d(Al, tmA, DMODEL + kx, bm, FULL + 8*s);
                tma2d(Bs, tmB, kx,          bn, FULL + 8*s);
            }
        }
    }

    const int grp = lane >> 2;
    const int qd  = lane & 3;
#pragma unroll
    for (int mi = 0; mi < 2; mi++) {
#pragma unroll
        for (int nj = 0; nj < 8; nj++) {
            const int col = bn + wn*64 + nj*8 + qd*2;
            const float b0 = __ldg(&bias[col]);
            const float b1 = __ldg(&bias[col + 1]);
#pragma unroll
            for (int half = 0; half < 2; half++) {
                const int m = bm + wm*32 + mi*16 + grp + half*8;
                const float v0 = acc[mi][nj][2*half+0] + b0;
                const float v1 = acc[mi][nj][2*half+1] + b1;
                if (MODE == 0) {
                    *(float2*)&C[(size_t)m * DMODEL + col] = make_float2(v0, v1);
                } else {
                    const int b = m >> 11, srow = m & 2047;
                    const int h = col >> 6, d = col & 63;
                    const size_t off = (((size_t)b * NHEAD + h) * SEQ + srow) * DHEAD + d;
                    *(uint32_t*)&Ohi[off] = pack2_f16(v0, v1);
                }
            }
        }
    }
}

struct QkvMaps { CUtensorMap a[3]; CUtensorMap b[3]; };

__global__ void __launch_bounds__(256, 2)
gemm_qkv(const __grid_constant__ QkvMaps maps,
         const float* __restrict__ biasc, __half* __restrict__ qkvbase,
         unsigned* cnt)
{
    const int i = blockIdx.z;
    gemm_core<1, 1>(&maps.a[i], &maps.b[i], biasc + i * DMODEL, nullptr,
                    qkvbase + (size_t)i * QKVPART, cnt, 0,
                    blockIdx.y * 128, blockIdx.x * 128);
}

__global__ void __launch_bounds__(256, 2)
gemm_out(const __grid_constant__ CUtensorMap tmA,
         const __grid_constant__ CUtensorMap tmB,
         const float* __restrict__ bias, float* __restrict__ C,
         unsigned* cnt)
{
    gemm_core<0, 2>(&tmA, &tmB, bias, C, nullptr, cnt, blockIdx.y,
                    blockIdx.y * 128, blockIdx.x * 128);
}

// ---------------------------------------------------------------------------
// Flash attention, pure fp16 HMMA, f16x2 exp2 softmax. Early GDC_LAUNCH;
// epilogue publishes AO readiness per 128-row block via release atomics.
// ---------------------------------------------------------------------------
#define QT 128
#define KT 64
#define AT_TILEQ  16384
#define AT_TILEKV 8192
#define AT_STAGE  (2*AT_TILEKV)      // Kh, Vh
#define ASMEM (1024 + AT_TILEQ + 2*AT_STAGE)

__global__ void __launch_bounds__(256, 2)
attn_mma(const __grid_constant__ CUtensorMap tmQ,
         const __grid_constant__ CUtensorMap tmK,
         const __grid_constant__ CUtensorMap tmV,
         __half* __restrict__ AO, unsigned* cnt)
{
    extern __shared__ char smraw[];
    const uint32_t sb = smem_u32(smraw);
    const uint32_t tiles = (sb + 1024) & ~1023u;
    const uint32_t Qs = tiles;
    const uint32_t STG = tiles + AT_TILEQ;
    const int tid = threadIdx.x, lane = tid & 31, wid = tid >> 5;
    const int bh = blockIdx.y;
    const int q0 = blockIdx.x * QT;
    const int gy = bh * SEQ;

    const uint32_t BQ = sb, BF = sb + 8, BE = sb + 24;
    if (tid == 0) {
        MBARRIER_INIT(BQ, 1);
        MBARRIER_INIT(BF + 0, 1);
        MBARRIER_INIT(BF + 8, 1);
        MBARRIER_INIT(BE + 0, 8);
        MBARRIER_INIT(BE + 8, 8);
    }
    __syncthreads();

    GDC_WAIT();      // Q/K/V produced by gemm_qkv (also orders cnt zeroing)
    GDC_LAUNCH();    // early: gemm_out enforces its dependency via cnt spins

    if (tid == 0) {
        MBARRIER_EXPECT_TX(BQ, AT_TILEQ);
        tma2d(Qs, &tmQ, 0, gy + q0, BQ);
#pragma unroll
        for (int s = 0; s < 2; s++) {
            const uint32_t st = STG + s*AT_STAGE;
            MBARRIER_EXPECT_TX(BF + 8*s, AT_STAGE);
            tma2d(st,              &tmK, 0, gy + s*KT, BF + 8*s);
            tma2d(st + AT_TILEKV,  &tmV, 0, gy + s*KT, BF + 8*s);
        }
    }

    float m_run[2] = { -1e30f, -1e30f };
    float l_run[2] = { 0.f, 0.f };
    float o_acc[8][4];
#pragma unroll
    for (int i = 0; i < 8; i++)
#pragma unroll
        for (int j = 0; j < 4; j++) o_acc[i][j] = 0.f;

    MBARRIER_WAIT_PARITY(BQ, 0);

    const int r0q = wid * 16;
    const int la7 = lane & 7;
    const int g01 = (lane >> 3) & 1;
    const int g23 = lane >> 4;

    uint32_t qf[4][4];
#pragma unroll
    for (int j = 0; j < 4; j++) {
        const int rr = r0q + la7 + g01*8;
        const int uu = 2*j + g23;
        ldsm_x4(qf[j][0], qf[j][1], qf[j][2], qf[j][3], ldsm_addr(Qs, rr, uu));
    }

    for (int kt = 0; kt < SEQ / KT; kt++) {
        const int s = kt & 1, ph = (kt >> 1) & 1;
        MBARRIER_WAIT_PARITY(BF + 8*s, ph);
        const uint32_t Kh = STG + s*AT_STAGE;
        const uint32_t Vh = Kh + AT_TILEKV;

        float sf[8][4];
#pragma unroll
        for (int i = 0; i < 8; i++)
#pragma unroll
            for (int j = 0; j < 4; j++) sf[i][j] = 0.f;

#pragma unroll
        for (int j = 0; j < 4; j++) {
#pragma unroll
            for (int np = 0; np < 4; np++) {
                const int rr = np*16 + la7 + g23*8;
                const int uu = 2*j + g01;
                uint32_t k0,k1,k2,k3;
                ldsm_x4(k0,k1,k2,k3, ldsm_addr(Kh, rr, uu));
                mma16816h(sf[2*np+0], qf[j], k0, k1);
                mma16816h(sf[2*np+1], qf[j], k2, k3);
            }
        }

        // ---- online softmax: exp2 in fp16x2 pairs (P fragments) ----
        uint32_t psf[8][2];
#pragma unroll
        for (int hf = 0; hf < 2; hf++) {
            float mx = -1e30f;
#pragma unroll
            for (int nt = 0; nt < 8; nt++)
                mx = fmaxf(mx, fmaxf(sf[nt][2*hf], sf[nt][2*hf+1]));
            mx = fmaxf(mx, __shfl_xor_sync(0xffffffffu, mx, 1));
            mx = fmaxf(mx, __shfl_xor_sync(0xffffffffu, mx, 2));
            const float mnew = fmaxf(m_run[hf], mx);
            const float corr = ex2(m_run[hf] - mnew);
            float sum = 0.f;
#pragma unroll
            for (int nt = 0; nt < 8; nt++) {
                const uint32_t u = pack2_f16(sf[nt][2*hf] - mnew,
                                             sf[nt][2*hf+1] - mnew);
                const uint32_t p2 = ex2_f16x2(u);
                psf[nt][hf] = p2;
                const float2 pf = __half22float2(*reinterpret_cast<const __half2*>(&p2));
                sum += pf.x + pf.y;
            }
            sum += __shfl_xor_sync(0xffffffffu, sum, 1);
            sum += __shfl_xor_sync(0xffffffffu, sum, 2);
            l_run[hf] = l_run[hf] * corr + sum;
            m_run[hf] = mnew;
#pragma unroll
            for (int nt = 0; nt < 8; nt++) {
                o_acc[nt][2*hf]   *= corr;
                o_acc[nt][2*hf+1] *= corr;
            }
        }

        // ---- O += P V ----
#pragma unroll
        for (int j = 0; j < 4; j++) {
            uint32_t ph16[4];
#pragma unroll
            for (int t = 0; t < 4; t++)
                ph16[t] = psf[2*j + (t >> 1)][t & 1];
#pragma unroll
            for (int np = 0; np < 4; np++) {
                const int rr = 16*j + la7 + g01*8;
                const int uu = 2*np + g23;
                uint32_t v0,v1,v2,v3;
                ldsm_x4_t(v0,v1,v2,v3, ldsm_addr(Vh, rr, uu));
                mma16816h(o_acc[2*np+0], ph16, v0, v1);
                mma16816h(o_acc[2*np+1], ph16, v2, v3);
            }
        }

        if (lane == 0) MBARRIER_ARRIVE(BE + 8*s);
        if (tid == 0 && kt + 2 < SEQ / KT) {
            MBARRIER_WAIT_PARITY(BE + 8*s, ph);
            const uint32_t st = STG + s*AT_STAGE;
            MBARRIER_EXPECT_TX(BF + 8*s, AT_STAGE);
            tma2d(st,             &tmK, 0, gy + (kt+2)*KT, BF + 8*s);
            tma2d(st + AT_TILEKV, &tmV, 0, gy + (kt+2)*KT, BF + 8*s);
        }
    }

    const int b = bh >> 4, h = bh & 15;
#pragma unroll
    for (int hf = 0; hf < 2; hf++) {
        const float inv = 1.f / l_run[hf];
        const int srow = q0 + r0q + (lane >> 2) + hf*8;
#pragma unroll
        for (int nt = 0; nt < 8; nt++) {
            const int d = nt*8 + (lane & 3)*2;
            const float f0 = o_acc[nt][2*hf]   * inv;
            const float f1 = o_acc[nt][2*hf+1] * inv;
            uint32_t hp, lp;
            split_pack2_f16(f0, f1, hp, lp);
            const size_t base = ((size_t)b * SEQ + srow) * 2 * DMODEL + h * DHEAD + d;
            *(uint32_t*)&AO[base]          = hp;
            *(uint32_t*)&AO[base + DMODEL] = lp;
        }
    }

    // publish readiness of AO rows [b*2048 + q0, +128) : block mb = b*16 + qblk
    __threadfence();
    __syncthreads();
    if (tid == 0) red_rel_add(&cnt[b * (SEQ/128) + blockIdx.x], 1u);
}

// ---------------------------------------------------------------------------
// Host
// ---------------------------------------------------------------------------
typedef CUresult (*PFN_tmEncode)(CUtensorMap*, CUtensorMapDataType, cuuint32_t, void*,
                                 const cuuint64_t*, const cuuint64_t*, const cuuint32_t*,
                                 const cuuint32_t*, CUtensorMapInterleave, CUtensorMapSwizzle,
                                 CUtensorMapL2promotion, CUtensorMapFloatOOBfill);

static void make_map(PFN_tmEncode enc, CUtensorMap* m, void* p, uint64_t rows,
                     uint64_t width, uint32_t b0, uint32_t b1)
{
    cuuint64_t dims[2]    = { width, rows };
    cuuint64_t strides[1] = { width * 2 };
    cuuint32_t box[2]     = { b0, b1 };
    cuuint32_t es[2]      = { 1, 1 };
    enc(m, CU_TENSOR_MAP_DATA_TYPE_FLOAT16, 2, p, dims, strides, box, es,
        CU_TENSOR_MAP_INTERLEAVE_NONE, CU_TENSOR_MAP_SWIZZLE_128B,
        CU_TENSOR_MAP_L2_PROMOTION_L2_128B, CU_TENSOR_MAP_FLOAT_OOB_FILL_NONE);
}

extern "C" void kernel_launch(void* const* d_in, const int* in_sizes, int n_in,
                              void* d_out, int out_size)
{
    const float* act[3] = { (const float*)d_in[0], (const float*)d_in[1], (const float*)d_in[2] };
    const float* W[4]   = { (const float*)d_in[3], (const float*)d_in[5], (const float*)d_in[7], (const float*)d_in[9] };
    const float* bia[4] = { (const float*)d_in[4], (const float*)d_in[6], (const float*)d_in[8], (const float*)d_in[10] };
    float* out = (float*)d_out;

    __half *pact, *pwt, *pao, *pqkv;
    float* pbc;
    unsigned* pcnt;
    cudaGetSymbolAddress((void**)&pact, g_act);
    cudaGetSymbolAddress((void**)&pwt,  g_wt);
    cudaGetSymbolAddress((void**)&pao,  g_ao);
    cudaGetSymbolAddress((void**)&pqkv, g_qkvs);
    cudaGetSymbolAddress((void**)&pbc,  g_biasc);
    cudaGetSymbolAddress((void**)&pcnt, g_cnt);

    PFN_tmEncode enc = nullptr;
    cudaDriverEntryPointQueryResult qr;
    cudaGetDriverEntryPointByVersion("cuTensorMapEncodeTiled", (void**)&enc, 12000,
                                     cudaEnableDefault, &qr);

    const size_t WM = (size_t)DMODEL * DMODEL;

    static QkvMaps qkvmaps;
    static CUtensorMap mAao, mBo, mQKV[3];
    for (int i = 0; i < 3; i++) {
        make_map(enc, &qkvmaps.a[i], pact + (size_t)i * MTOT * DMODEL, MTOT, DMODEL, BK, 128);
        make_map(enc, &qkvmaps.b[i], pwt + (size_t)i * WM, DMODEL, DMODEL, BK, 128);
    }
    make_map(enc, &mAao, pao, MTOT, 2*DMODEL, BK, 128);
    make_map(enc, &mBo, pwt + 3*WM, DMODEL, DMODEL, BK, 128);
    for (int i = 0; i < 3; i++)
        make_map(enc, &mQKV[i], pqkv + i * QKVPART, (uint64_t)BHTOT * SEQ, DHEAD,
                 DHEAD, (i == 0) ? QT : KT);

    cudaFuncSetAttribute(gemm_qkv, cudaFuncAttributeMaxDynamicSharedMemorySize, GSMEM);
    cudaFuncSetAttribute(gemm_out, cudaFuncAttributeMaxDynamicSharedMemorySize, GSMEM);
    cudaFuncSetAttribute(attn_mma, cudaFuncAttributeMaxDynamicSharedMemorySize, ASMEM);

    cudaLaunchAttribute pdl;
    pdl.id = cudaLaunchAttributeProgrammaticStreamSerialization;
    pdl.val.programmaticStreamSerializationAllowed = 1;

    // 1. fused preprocessing (primary)
    pre_kernel<<<PRE_TOTAL, 256>>>(act[0], act[1], act[2],
                                   W[0], W[1], W[2], W[3],
                                   bia[0], bia[1], bia[2],
                                   pact, pwt, pbc);

    // 2. fused QKV projections (PDL-dependent on pre; zeroes g_cnt)
    {
        cudaLaunchConfig_t cfg = {};
        cfg.gridDim = dim3(DMODEL/128, MTOT/128, 3);
        cfg.blockDim = dim3(256, 1, 1);
        cfg.dynamicSmemBytes = GSMEM;
        cfg.stream = 0;
        cfg.attrs = &pdl;
        cfg.numAttrs = 1;
        cudaLaunchKernelEx(&cfg, gemm_qkv, qkvmaps, (const float*)pbc, pqkv, pcnt);
    }

    // 3. attention (PDL-dependent on qkv; early launch of gemm_out)
    {
        cudaLaunchConfig_t cfg = {};
        cfg.gridDim = dim3(SEQ / QT, BHTOT, 1);
        cfg.blockDim = dim3(256, 1, 1);
        cfg.dynamicSmemBytes = ASMEM;
        cfg.stream = 0;
        cfg.attrs = &pdl;
        cfg.numAttrs = 1;
        cudaLaunchKernelEx(&cfg, attn_mma, mQKV[0], mQKV[1], mQKV[2], pao, pcnt);
    }

    // 4. output projection (PDL-dependent on attention; gated by g_cnt)
    {
        cudaLaunchConfig_t cfg = {};
        cfg.gridDim = dim3(DMODEL/128, MTOT/128, 1);
        cfg.blockDim = dim3(256, 1, 1);
        cfg.dynamicSmemBytes = GSMEM;
        cfg.stream = 0;
        cfg.attrs = &pdl;
        cfg.numAttrs = 1;
        cudaLaunchKernelEx(&cfg, gemm_out, mAao, mBo, (const float*)bia[3], out, pcnt);
    }
}